// round 1
// baseline (speedup 1.0000x reference)
#include <cuda_runtime.h>
#include <cuda_bf16.h>

// Problem dims (fixed)
#define BB 8
#define SS 2048
#define DD 1024
#define HH 2048
#define AA 128
#define EE 8
#define MM (BB*SS)   // 16384 tokens

// -------- scratch (device globals; no allocation allowed) --------
__device__ float g_Yg[MM*HH];          // gate pre-act
__device__ float g_Yu[MM*HH];          // up pre-act
__device__ float g_Hid[MM*HH];         // hidden0 = silu(gate)*up
__device__ float g_Pre[MM*AA];
__device__ float g_Ain[MM*AA];         // LN(pre)
__device__ float g_Post[MM*AA];
__device__ float g_Aout[MM*AA];        // LN(post)
__device__ float g_AiT[BB*AA*SS];      // adapt_in transposed per batch [A,S]
__device__ float g_AW[BB*SS*SS];       // attention weights
__device__ float g_Adapt[MM*AA];
__device__ float g_Eall[MM*EE*AA];     // all experts' pre-LN activations
__device__ float g_Ecomp[MM*AA];       // selected+LN'd expert activation (0 if none)
__device__ float g_Wcomb[DD*AA];       // w_out @ w_eproj
__device__ float g_W2[DD*AA];          // w_down @ w_aproj
__device__ float g_Tep[AA*HH];         // w_eproj^T
__device__ float g_Tap[AA*HH];         // w_aproj^T

// ============================================================
// Generic SGEMM-NT: C[M,N] (+)= alpha * A[M,K] * B[N,K]^T
// row-major A,B (K contiguous). Batched via grid.z = batch*ksplit.
// Requires M%128==0, N%128==0, (K/ksplit)%8==0.
// atomic=0: plain store.  atomic=1: atomicAdd.
// ============================================================
__global__ __launch_bounds__(256, 2)
void sgemm_nt(const float* __restrict__ A, const float* __restrict__ B,
              float* __restrict__ C,
              int M, int N, int K,
              long sA, long sB, long sC,
              int ksplit, float alpha, int atomic)
{
    int bz = blockIdx.z;
    int batch = bz / ksplit;
    int ik    = bz % ksplit;
    int Kc    = K / ksplit;
    A += (long)batch * sA + (long)ik * Kc;
    B += (long)batch * sB + (long)ik * Kc;
    C += (long)batch * sC;

    __shared__ float As[8][128];
    __shared__ float Bs[8][128];

    int tid = threadIdx.x;
    int lr  = tid >> 1;           // 0..127
    int lk  = (tid & 1) << 2;     // 0 or 4

    const float* Ap = A + (long)(blockIdx.y * 128 + lr) * K + lk;
    const float* Bp = B + (long)(blockIdx.x * 128 + lr) * K + lk;

    float acc[8][8];
#pragma unroll
    for (int i = 0; i < 8; i++)
#pragma unroll
        for (int j = 0; j < 8; j++) acc[i][j] = 0.f;

    int tr = (tid >> 4) << 3;     // row offset within tile
    int tc = (tid & 15) << 3;     // col offset within tile

    for (int k0 = 0; k0 < Kc; k0 += 8) {
        float4 a4 = *(const float4*)(Ap + k0);
        float4 b4 = *(const float4*)(Bp + k0);
        As[lk + 0][lr] = a4.x; As[lk + 1][lr] = a4.y;
        As[lk + 2][lr] = a4.z; As[lk + 3][lr] = a4.w;
        Bs[lk + 0][lr] = b4.x; Bs[lk + 1][lr] = b4.y;
        Bs[lk + 2][lr] = b4.z; Bs[lk + 3][lr] = b4.w;
        __syncthreads();
#pragma unroll
        for (int k = 0; k < 8; k++) {
            float ra[8], rb[8];
            *(float4*)(ra    ) = *(const float4*)&As[k][tr    ];
            *(float4*)(ra + 4) = *(const float4*)&As[k][tr + 4];
            *(float4*)(rb    ) = *(const float4*)&Bs[k][tc    ];
            *(float4*)(rb + 4) = *(const float4*)&Bs[k][tc + 4];
#pragma unroll
            for (int i = 0; i < 8; i++)
#pragma unroll
                for (int j = 0; j < 8; j++)
                    acc[i][j] = fmaf(ra[i], rb[j], acc[i][j]);
        }
        __syncthreads();
    }

    long crow0 = (long)(blockIdx.y * 128 + tr) * N + blockIdx.x * 128 + tc;
    if (!atomic) {
#pragma unroll
        for (int i = 0; i < 8; i++) {
            float4 v0, v1;
            v0.x = alpha * acc[i][0]; v0.y = alpha * acc[i][1];
            v0.z = alpha * acc[i][2]; v0.w = alpha * acc[i][3];
            v1.x = alpha * acc[i][4]; v1.y = alpha * acc[i][5];
            v1.z = alpha * acc[i][6]; v1.w = alpha * acc[i][7];
            *(float4*)(C + crow0 + (long)i * N)     = v0;
            *(float4*)(C + crow0 + (long)i * N + 4) = v1;
        }
    } else {
#pragma unroll
        for (int i = 0; i < 8; i++)
#pragma unroll
            for (int j = 0; j < 8; j++)
                atomicAdd(C + crow0 + (long)i * N + j, alpha * acc[i][j]);
    }
}

// ============================================================
// Small helpers
// ============================================================
__global__ void zero_kernel(float* p, long n)
{
    long i = (long)blockIdx.x * blockDim.x + threadIdx.x;
    long stride = (long)gridDim.x * blockDim.x;
    for (; i < n; i += stride) p[i] = 0.f;
}

// out[b][c][r] = in[b][r][c]   (tiled transpose)
__global__ void transpose_kernel(const float* __restrict__ in, float* __restrict__ out,
                                 int R, int C, long sIn, long sOut)
{
    __shared__ float tile[32][33];
    in  += (long)blockIdx.z * sIn;
    out += (long)blockIdx.z * sOut;
    int r0 = blockIdx.y * 32, c0 = blockIdx.x * 32;
    int tx = threadIdx.x, ty = threadIdx.y;
#pragma unroll
    for (int i = 0; i < 32; i += 8)
        tile[ty + i][tx] = in[(long)(r0 + ty + i) * C + c0 + tx];
    __syncthreads();
#pragma unroll
    for (int i = 0; i < 32; i += 8)
        out[(long)(c0 + ty + i) * R + r0 + tx] = tile[tx][ty + i];
}

__device__ __forceinline__ float2 block_mean_var_128(float v)
{
    float s = v, s2 = v * v;
#pragma unroll
    for (int o = 16; o > 0; o >>= 1) {
        s  += __shfl_xor_sync(0xffffffffu, s,  o);
        s2 += __shfl_xor_sync(0xffffffffu, s2, o);
    }
    __shared__ float sh[8];
    int w = threadIdx.x >> 5;
    if ((threadIdx.x & 31) == 0) { sh[w] = s; sh[4 + w] = s2; }
    __syncthreads();
    s  = sh[0] + sh[1] + sh[2] + sh[3];
    s2 = sh[4] + sh[5] + sh[6] + sh[7];
    __syncthreads();
    float m = s * (1.f / 128.f);
    return make_float2(m, s2 * (1.f / 128.f) - m * m);
}

// LN over rows of length 128: one block (128 threads) per row
__global__ void ln_kernel(const float* __restrict__ in, float* __restrict__ out,
                          const float* __restrict__ g, const float* __restrict__ b)
{
    long row = blockIdx.x;
    int  t   = threadIdx.x;
    float v  = in[row * 128 + t];
    float2 mv = block_mean_var_128(v);
    float inv = rsqrtf(mv.y + 1e-5f);
    out[row * 128 + t] = (v - mv.x) * inv * g[t] + b[t];
}

__global__ void silu_mul_kernel(const float* __restrict__ G, const float* __restrict__ U,
                                float* __restrict__ H, long n)
{
    long i = (long)blockIdx.x * blockDim.x + threadIdx.x;
    long stride = (long)gridDim.x * blockDim.x;
    for (; i < n; i += stride) {
        float gv = G[i];
        float s  = gv / (1.f + expf(-gv));
        H[i] = s * U[i];
    }
}

__global__ void siluclip_kernel(float* __restrict__ P, long n)
{
    long i = (long)blockIdx.x * blockDim.x + threadIdx.x;
    long stride = (long)gridDim.x * blockDim.x;
    for (; i < n; i += stride) {
        float v = P[i];
        v = fminf(5.f, fmaxf(-5.f, v));
        P[i] = v / (1.f + expf(-v));
    }
}

// Per-token: pick LAST expert with ew>0 (later experts win), LN its activation
// with that expert's eln params; zeros if no expert active.
__global__ void expert_select_kernel(const float* __restrict__ ew,
                                     const float* __restrict__ Eall,
                                     const float* __restrict__ eln_g,
                                     const float* __restrict__ eln_b,
                                     float* __restrict__ Ecomp)
{
    long m = blockIdx.x;
    int  t = threadIdx.x;
    __shared__ int sidx;
    if (t == 0) {
        int idx = -1;
        const float* w = ew + m * EE;
#pragma unroll
        for (int i = 0; i < EE; i++) if (w[i] > 0.f) idx = i;
        sidx = idx;
    }
    __syncthreads();
    int idx = sidx;
    float o = 0.f;
    if (idx >= 0) {
        float v = Eall[m * (EE * AA) + idx * AA + t];
        float2 mv = block_mean_var_128(v);
        float inv = rsqrtf(mv.y + 1e-5f);
        o = (v - mv.x) * inv * eln_g[idx * AA + t] + eln_b[idx * AA + t];
    }
    Ecomp[m * AA + t] = o;
}

// ============================================================
// Launch
// ============================================================
extern "C" void kernel_launch(void* const* d_in, const int* in_sizes, int n_in,
                              void* d_out, int out_size)
{
    const float* x       = (const float*)d_in[0];
    const float* ew      = (const float*)d_in[1];
    const float* w_up    = (const float*)d_in[2];
    const float* w_gate  = (const float*)d_in[3];
    const float* w_down  = (const float*)d_in[4];
    const float* w_pre   = (const float*)d_in[5];
    const float* w_post  = (const float*)d_in[6];
    const float* an_g    = (const float*)d_in[7];
    const float* an_b    = (const float*)d_in[8];
    const float* w_aproj = (const float*)d_in[9];
    const float* w_exp   = (const float*)d_in[10];
    const float* eln_g   = (const float*)d_in[11];
    const float* eln_b   = (const float*)d_in[12];
    const float* w_eproj = (const float*)d_in[13];
    const float* w_out   = (const float*)d_in[14];
    float* out = (float*)d_out;

    float *Yg, *Yu, *Hid, *Pre, *Ain, *Post, *Aout, *AiT, *AW, *Adapt,
          *Eall, *Ecomp, *Wcomb, *W2, *Tep, *Tap;
    cudaGetSymbolAddress((void**)&Yg,    g_Yg);
    cudaGetSymbolAddress((void**)&Yu,    g_Yu);
    cudaGetSymbolAddress((void**)&Hid,   g_Hid);
    cudaGetSymbolAddress((void**)&Pre,   g_Pre);
    cudaGetSymbolAddress((void**)&Ain,   g_Ain);
    cudaGetSymbolAddress((void**)&Post,  g_Post);
    cudaGetSymbolAddress((void**)&Aout,  g_Aout);
    cudaGetSymbolAddress((void**)&AiT,   g_AiT);
    cudaGetSymbolAddress((void**)&AW,    g_AW);
    cudaGetSymbolAddress((void**)&Adapt, g_Adapt);
    cudaGetSymbolAddress((void**)&Eall,  g_Eall);
    cudaGetSymbolAddress((void**)&Ecomp, g_Ecomp);
    cudaGetSymbolAddress((void**)&Wcomb, g_Wcomb);
    cudaGetSymbolAddress((void**)&W2,    g_W2);
    cudaGetSymbolAddress((void**)&Tep,   g_Tep);
    cudaGetSymbolAddress((void**)&Tap,   g_Tap);

    dim3 tb32(32, 8);

    // ---- zero buffers used as split-K atomic targets ----
    zero_kernel<<<256, 256>>>(Pre,   (long)MM * AA);
    zero_kernel<<<256, 256>>>(Post,  (long)MM * AA);
    zero_kernel<<<256, 256>>>(Adapt, (long)MM * AA);
    zero_kernel<<<64,  256>>>(Wcomb, (long)DD * AA);
    zero_kernel<<<64,  256>>>(W2,    (long)DD * AA);

    // ---- weight-only precomputes ----
    transpose_kernel<<<dim3(AA / 32, HH / 32, 1), tb32>>>(w_eproj, Tep, HH, AA, 0, 0);
    transpose_kernel<<<dim3(AA / 32, HH / 32, 1), tb32>>>(w_aproj, Tap, HH, AA, 0, 0);
    // Wcomb = w_out @ w_eproj  (split-K 16)
    sgemm_nt<<<dim3(1, DD / 128, 16), 256>>>(w_out,  Tep, Wcomb, DD, AA, HH, 0, 0, 0, 16, 1.f, 1);
    // W2 = w_down @ w_aproj
    sgemm_nt<<<dim3(1, DD / 128, 16), 256>>>(w_down, Tap, W2,    DD, AA, HH, 0, 0, 0, 16, 1.f, 1);

    // ---- up / gate / hidden0 ----
    sgemm_nt<<<dim3(HH / 128, MM / 128, 1), 256>>>(x, w_gate, Yg, MM, HH, DD, 0, 0, 0, 1, 1.f, 0);
    sgemm_nt<<<dim3(HH / 128, MM / 128, 1), 256>>>(x, w_up,   Yu, MM, HH, DD, 0, 0, 0, 1, 1.f, 0);
    silu_mul_kernel<<<4096, 256>>>(Yg, Yu, Hid, (long)MM * HH);

    // ---- pre / adapt_in ----
    sgemm_nt<<<dim3(1, MM / 128, 4), 256>>>(x, w_pre, Pre, MM, AA, DD, 0, 0, 0, 4, 1.f, 1);
    ln_kernel<<<MM, 128>>>(Pre, Ain, an_g, an_b);

    // ---- post / adapt_out ----
    sgemm_nt<<<dim3(1, MM / 128, 4), 256>>>(Hid, w_post, Post, MM, AA, HH, 0, 0, 0, 4, 1.f, 1);
    ln_kernel<<<MM, 128>>>(Post, Aout, an_g, an_b);

    // ---- adapt attention (linear attention, no softmax) ----
    transpose_kernel<<<dim3(AA / 32, SS / 32, BB), tb32>>>(Ain, AiT, SS, AA,
                                                           (long)SS * AA, (long)SS * AA);
    // AW[b] = Ain[b] @ Aout[b]^T   [S,S]
    sgemm_nt<<<dim3(SS / 128, SS / 128, BB), 256>>>(Ain, Aout, AW, SS, SS, AA,
                                                    (long)SS * AA, (long)SS * AA, (long)SS * SS,
                                                    1, 1.f, 0);
    siluclip_kernel<<<4096, 256>>>(AW, (long)BB * SS * SS);
    // Adapt[b] = AW[b] @ Ain[b]  -> NT with AiT; batch 8 x splitK 4
    sgemm_nt<<<dim3(1, SS / 128, BB * 4), 256>>>(AW, AiT, Adapt, SS, AA, SS,
                                                 (long)SS * SS, (long)AA * SS, (long)SS * AA,
                                                 4, 1.f, 1);

    // ---- out = hidden0 @ w_down^T  (writes every element; d_out is poisoned) ----
    sgemm_nt<<<dim3(DD / 128, MM / 128, 1), 256>>>(Hid, w_down, out, MM, DD, HH, 0, 0, 0, 1, 1.f, 0);
    // out += 0.1 * Adapt @ W2^T
    sgemm_nt<<<dim3(DD / 128, MM / 128, 1), 256>>>(Adapt, W2, out, MM, DD, AA, 0, 0, 0, 1, 0.1f, 1);

    // ---- experts ----
    // Eall = Pre @ w_exp_flat^T   (w_exp [E,A,A] flattened to [E*A, A])
    sgemm_nt<<<dim3(EE * AA / 128, MM / 128, 1), 256>>>(Pre, w_exp, Eall, MM, EE * AA, AA,
                                                        0, 0, 0, 1, 1.f, 0);
    expert_select_kernel<<<MM, 128>>>(ew, Eall, eln_g, eln_b, Ecomp);
    // out += 0.1 * Ecomp @ Wcomb^T
    sgemm_nt<<<dim3(DD / 128, MM / 128, 1), 256>>>(Ecomp, Wcomb, out, MM, DD, AA, 0, 0, 0, 1, 0.1f, 1);
}

// round 3
// speedup vs baseline: 1.4346x; 1.4346x over previous
#include <cuda_runtime.h>
#include <cuda_bf16.h>
#include <cstdint>

// Problem dims (fixed)
#define BB 8
#define SS 2048
#define DD 1024
#define HH 2048
#define AA 128
#define EE 8
#define MM (BB*SS)   // 16384 tokens

// tcgen05 is arch-SPECIFIC (sm_103a). Only use it in an arch-specific pass.
#if defined(__CUDA_ARCH_FEAT_SM103_ALL)
#define TCPATH 1
#endif

// -------- scratch (device globals; no allocation allowed) --------
__device__ float g_Yg[MM*HH];          // gate pre-act
__device__ float g_Hid[MM*HH];         // hidden0 = silu(gate)*up
__device__ float g_Pre[MM*AA];
__device__ float g_Ain[MM*AA];         // LN(pre)
__device__ float g_Post[MM*AA];
__device__ float g_Aout[MM*AA];        // LN(post)
__device__ float g_AiT[BB*AA*SS];      // adapt_in transposed per batch [A,S]
__device__ float g_AW[(long)BB*SS*SS]; // attention weights (post silu-clip)
__device__ float g_Adapt[MM*AA];
__device__ float g_Eall[MM*EE*AA];     // all experts' pre-LN activations
__device__ float g_Ecomp[MM*AA];       // selected+LN'd expert activation
__device__ float g_Wcomb[DD*AA];       // w_out @ w_eproj
__device__ float g_W2[DD*AA];          // w_down @ w_aproj
__device__ float g_Tep[AA*HH];         // w_eproj^T
__device__ float g_Tap[AA*HH];         // w_aproj^T

// ============================================================
// common helpers
// ============================================================
__device__ __forceinline__ float silu_f(float v) {
    return v * __frcp_rn(1.f + __expf(-v));
}

__device__ __forceinline__ uint32_t f2tf32(float f) {
    uint32_t u;
    asm("cvt.rna.tf32.f32 %0, %1;" : "=r"(u) : "f"(f));
    return u;
}

#ifdef TCPATH
// ============================================================
// tcgen05 helpers (sm_103a-specific pass only)
// ============================================================
__device__ __forceinline__ uint32_t smem_u32(const void* p) {
    uint32_t a;
    asm("{ .reg .u64 t; cvta.to.shared.u64 t, %1; cvt.u32.u64 %0, t; }"
        : "=r"(a) : "l"(p));
    return a;
}

__device__ __forceinline__ uint32_t elect1() {
    uint32_t p;
    asm volatile("{\n\t.reg .pred p;\n\telect.sync _|p, 0xFFFFFFFF;\n\t"
                 "selp.b32 %0, 1, 0, p;\n\t}" : "=r"(p));
    return p;
}

#define MBAR_INIT(addr, cnt) \
    asm volatile("mbarrier.init.shared.b64 [%0], %1;" :: "r"(addr), "r"(cnt) : "memory")

__device__ __forceinline__ void mbar_wait(uint32_t mbar, uint32_t parity) {
    uint32_t done;
    asm volatile("{\n\t.reg .pred p;\n\t"
                 "mbarrier.try_wait.parity.acquire.cta.shared::cta.b64 p, [%1], %2;\n\t"
                 "selp.b32 %0, 1, 0, p;\n\t}"
                 : "=r"(done) : "r"(mbar), "r"(parity) : "memory");
    while (!done) {
        asm volatile("{\n\t.reg .pred p;\n\t"
                     "mbarrier.try_wait.parity.acquire.cta.shared::cta.b64 p, [%1], %2, 0x989680;\n\t"
                     "selp.b32 %0, 1, 0, p;\n\t}"
                     : "=r"(done) : "r"(mbar), "r"(parity) : "memory");
    }
}

__device__ __forceinline__ void mma_tf32(uint32_t d, uint64_t da, uint64_t db,
                                         uint32_t idesc, uint32_t en) {
    asm volatile(
        "{\n\t.reg .pred p;\n\tsetp.ne.u32 p, %4, 0;\n\t"
        "tcgen05.mma.cta_group::1.kind::tf32 [%0], %1, %2, %3, {%5, %5, %5, %5}, p;\n\t}"
        :: "r"(d), "l"(da), "l"(db), "r"(idesc), "r"(en), "r"(0u)
        : "memory");
}

#define TC_COMMIT(mbar) \
    asm volatile("tcgen05.commit.cta_group::1.mbarrier::arrive::one.shared::cluster.b64 [%0];" \
                 :: "r"(mbar) : "memory")

#define LDTM_X32(r, addr) \
    asm volatile("tcgen05.ld.sync.aligned.32x32b.x32.b32 " \
        "{%0,%1,%2,%3,%4,%5,%6,%7,%8,%9,%10,%11,%12,%13,%14,%15," \
        "%16,%17,%18,%19,%20,%21,%22,%23,%24,%25,%26,%27,%28,%29,%30,%31}, [%32];" \
        : "=r"((r)[0]),  "=r"((r)[1]),  "=r"((r)[2]),  "=r"((r)[3]), \
          "=r"((r)[4]),  "=r"((r)[5]),  "=r"((r)[6]),  "=r"((r)[7]), \
          "=r"((r)[8]),  "=r"((r)[9]),  "=r"((r)[10]), "=r"((r)[11]), \
          "=r"((r)[12]), "=r"((r)[13]), "=r"((r)[14]), "=r"((r)[15]), \
          "=r"((r)[16]), "=r"((r)[17]), "=r"((r)[18]), "=r"((r)[19]), \
          "=r"((r)[20]), "=r"((r)[21]), "=r"((r)[22]), "=r"((r)[23]), \
          "=r"((r)[24]), "=r"((r)[25]), "=r"((r)[26]), "=r"((r)[27]), \
          "=r"((r)[28]), "=r"((r)[29]), "=r"((r)[30]), "=r"((r)[31]) \
        : "r"(addr))

static __device__ __forceinline__ uint64_t make_desc(uint32_t addr) {
    const uint64_t base = (2ULL << 61) | (1ULL << 46) | (64ULL << 32) | (1ULL << 16);
    return base | ((uint64_t)(addr >> 4) & 0x3FFF);
}

// idesc: dtype=F32(1<<4), atype=btype=TF32(2), N=128 ((N/8)<<17), M=128 ((M/16)<<24)
#define IDESC_TF32 ((1u << 4) | (2u << 7) | (2u << 10) | (16u << 17) | (8u << 24))
#endif  // TCPATH

// ============================================================
// tensor GEMM-NT:  C[M,N] (op)= alpha * A[M,K] * B[N,K]^T
// row-major, K contiguous in both. Tile 128x128, K-chunk 32.
// Requires M%128==0, N%128==0, K%32==0, K>=128.
// mode 0: C = alpha*acc
// mode 1: C += alpha*acc
// mode 2: C = silu(clip(acc, -5, 5))
// mode 3: C = silu(G[idx]) * acc      (fused SwiGLU; G same shape as C)
// grid = (N/128, M/128, batch), 128 threads.
// ============================================================
#define TCG_SMEM (1024 + 1024 + 65536)

__global__ __launch_bounds__(128)
void tc_gemm(const float* __restrict__ A, const float* __restrict__ B,
             float* __restrict__ C, const float* __restrict__ G,
             int M, int N, int K, long sA, long sB, long sC,
             float alpha, int mode)
{
    extern __shared__ char smem[];
    const int tid  = threadIdx.x;
    const int wid  = tid >> 5;
    const int lane = tid & 31;

    {
        long b = blockIdx.z;
        A += b * sA; B += b * sB; C += b * sC;
        if (mode == 3) G += b * sC;
    }
    const int m0 = blockIdx.y * 128, n0 = blockIdx.x * 128;
    const float* Ap = A + (long)m0 * K;
    const float* Bp = B + (long)n0 * K;
    const int nch = K >> 5;

#ifdef TCPATH
    // -------------------- tcgen05 path --------------------
    uint32_t sbase = smem_u32(smem);
    const uint32_t TM_PTR = sbase;
    const uint32_t MB0 = sbase + 16;
    const uint32_t MB1 = sbase + 24;
    uint32_t data0 = (sbase + 1024 + 1023) & ~1023u;
    char* dptr = smem + (data0 - sbase);

    if (wid == 0) {
        asm volatile("tcgen05.alloc.cta_group::1.sync.aligned.shared::cta.b32 [%0], %1;"
                     :: "r"(TM_PTR), "r"(128u) : "memory");
        asm volatile("tcgen05.relinquish_alloc_permit.cta_group::1.sync.aligned;");
    }
    if (tid == 0) { MBAR_INIT(MB0, 1); MBAR_INIT(MB1, 1); }
    __syncthreads();
    uint32_t tmem;
    asm volatile("ld.shared.b32 %0, [%1];" : "=r"(tmem) : "r"(TM_PTR));

    int ph0 = 0, ph1 = 0;
    for (int i = 0; i < nch; i++) {
        const int buf = i & 1;
        const uint32_t offA = buf * 32768u;
        const uint32_t offB = offA + 16384u;
        if (i >= 2) {
            if (buf == 0) { mbar_wait(MB0, ph0); ph0 ^= 1; }
            else          { mbar_wait(MB1, ph1); ph1 ^= 1; }
        }
        const int k0 = i << 5;
#pragma unroll
        for (int it = 0; it < 8; it++) {
            int idx = it * 128 + tid;
            int r = idx >> 3, q = idx & 7;
            uint32_t off = (uint32_t)(r * 128 + q * 16);
            uint32_t sw = off ^ ((off >> 3) & 0x70u);
            float4 va = *(const float4*)(Ap + (long)r * K + k0 + q * 4);
            float4 vb = *(const float4*)(Bp + (long)r * K + k0 + q * 4);
            uint4 ua = make_uint4(f2tf32(va.x), f2tf32(va.y), f2tf32(va.z), f2tf32(va.w));
            uint4 ub = make_uint4(f2tf32(vb.x), f2tf32(vb.y), f2tf32(vb.z), f2tf32(vb.w));
            *(uint4*)(dptr + offA + sw) = ua;
            *(uint4*)(dptr + offB + sw) = ub;
        }
        asm volatile("fence.proxy.async.shared::cta;" ::: "memory");
        __syncthreads();
        if (wid == 0 && elect1()) {
            uint64_t da = make_desc(data0 + offA);
            uint64_t db = make_desc(data0 + offB);
#pragma unroll
            for (int ks = 0; ks < 4; ks++)
                mma_tf32(tmem, da + ks * 2, db + ks * 2, IDESC_TF32,
                         (i > 0 || ks > 0) ? 1u : 0u);
            TC_COMMIT(buf == 0 ? MB0 : MB1);
        }
    }
    mbar_wait(MB0, ph0);
    mbar_wait(MB1, ph1);
    asm volatile("tcgen05.fence::after_thread_sync;" ::: "memory");

    float* Crow = C + (long)(m0 + wid * 32 + lane) * N + n0;
    const float* Grow = (mode == 3) ? (G + (long)(m0 + wid * 32 + lane) * N + n0) : nullptr;

#pragma unroll
    for (int cb = 0; cb < 128; cb += 32) {
        uint32_t r[32];
        LDTM_X32(r, tmem + cb);
        asm volatile("tcgen05.wait::ld.sync.aligned;" ::: "memory");
#pragma unroll
        for (int j = 0; j < 32; j += 4) {
            float4 v;
            v.x = __uint_as_float(r[j + 0]);
            v.y = __uint_as_float(r[j + 1]);
            v.z = __uint_as_float(r[j + 2]);
            v.w = __uint_as_float(r[j + 3]);
            if (mode == 0) {
                v.x *= alpha; v.y *= alpha; v.z *= alpha; v.w *= alpha;
            } else if (mode == 1) {
                float4 c = *(const float4*)(Crow + cb + j);
                v.x = fmaf(alpha, v.x, c.x); v.y = fmaf(alpha, v.y, c.y);
                v.z = fmaf(alpha, v.z, c.z); v.w = fmaf(alpha, v.w, c.w);
            } else if (mode == 2) {
                v.x = silu_f(fminf(5.f, fmaxf(-5.f, v.x)));
                v.y = silu_f(fminf(5.f, fmaxf(-5.f, v.y)));
                v.z = silu_f(fminf(5.f, fmaxf(-5.f, v.z)));
                v.w = silu_f(fminf(5.f, fmaxf(-5.f, v.w)));
            } else {
                float4 g = *(const float4*)(Grow + cb + j);
                v.x *= silu_f(g.x); v.y *= silu_f(g.y);
                v.z *= silu_f(g.z); v.w *= silu_f(g.w);
            }
            *(float4*)(Crow + cb + j) = v;
        }
    }
    asm volatile("tcgen05.fence::before_thread_sync;" ::: "memory");
    __syncthreads();
    if (wid == 0) {
        asm volatile("tcgen05.dealloc.cta_group::1.sync.aligned.b32 %0, %1;"
                     :: "r"(tmem), "r"(128u));
    }
#else
    // -------------------- mma.sync tf32 fallback --------------------
    // 4 warps in 2x2; warp tile 64x64; m16n8k8 tf32.
    uint32_t* As = (uint32_t*)smem;          // [128][36]
    uint32_t* Bs = As + 128 * 36;            // [128][36]

    const int warpM = wid >> 1, warpN = wid & 1;
    const int g  = lane >> 2;       // 0..7
    const int tk = lane & 3;        // 0..3

    float acc[4][8][4];
#pragma unroll
    for (int mt = 0; mt < 4; mt++)
#pragma unroll
        for (int nt = 0; nt < 8; nt++)
#pragma unroll
            for (int j = 0; j < 4; j++) acc[mt][nt][j] = 0.f;

    for (int i = 0; i < nch; i++) {
        __syncthreads();
        const int k0 = i << 5;
#pragma unroll
        for (int it = 0; it < 8; it++) {
            int idx = it * 128 + tid;
            int r = idx >> 3, q = idx & 7;
            float4 va = *(const float4*)(Ap + (long)r * K + k0 + q * 4);
            float4 vb = *(const float4*)(Bp + (long)r * K + k0 + q * 4);
            uint4 ua = make_uint4(f2tf32(va.x), f2tf32(va.y), f2tf32(va.z), f2tf32(va.w));
            uint4 ub = make_uint4(f2tf32(vb.x), f2tf32(vb.y), f2tf32(vb.z), f2tf32(vb.w));
            *(uint4*)(As + r * 36 + q * 4) = ua;
            *(uint4*)(Bs + r * 36 + q * 4) = ub;
        }
        __syncthreads();
#pragma unroll
        for (int kk = 0; kk < 4; kk++) {
            uint32_t af[4][4];
#pragma unroll
            for (int mt = 0; mt < 4; mt++) {
                int ra = warpM * 64 + mt * 16 + g;
                af[mt][0] = As[ra * 36 + kk * 8 + tk];
                af[mt][1] = As[(ra + 8) * 36 + kk * 8 + tk];
                af[mt][2] = As[ra * 36 + kk * 8 + tk + 4];
                af[mt][3] = As[(ra + 8) * 36 + kk * 8 + tk + 4];
            }
            uint32_t bf[8][2];
#pragma unroll
            for (int nt = 0; nt < 8; nt++) {
                int rb = warpN * 64 + nt * 8 + g;
                bf[nt][0] = Bs[rb * 36 + kk * 8 + tk];
                bf[nt][1] = Bs[rb * 36 + kk * 8 + tk + 4];
            }
#pragma unroll
            for (int mt = 0; mt < 4; mt++)
#pragma unroll
                for (int nt = 0; nt < 8; nt++) {
                    asm volatile(
                        "mma.sync.aligned.m16n8k8.row.col.f32.tf32.tf32.f32 "
                        "{%0,%1,%2,%3}, {%4,%5,%6,%7}, {%8,%9}, {%0,%1,%2,%3};"
                        : "+f"(acc[mt][nt][0]), "+f"(acc[mt][nt][1]),
                          "+f"(acc[mt][nt][2]), "+f"(acc[mt][nt][3])
                        : "r"(af[mt][0]), "r"(af[mt][1]), "r"(af[mt][2]), "r"(af[mt][3]),
                          "r"(bf[nt][0]), "r"(bf[nt][1]));
                }
        }
    }

    // epilogue
#pragma unroll
    for (int mt = 0; mt < 4; mt++) {
#pragma unroll
        for (int nt = 0; nt < 8; nt++) {
#pragma unroll
            for (int j = 0; j < 4; j++) {
                int row = m0 + warpM * 64 + mt * 16 + g + ((j >= 2) ? 8 : 0);
                int col = n0 + warpN * 64 + nt * 8 + tk * 2 + (j & 1);
                long ci = (long)row * N + col;
                float a = acc[mt][nt][j];
                float v;
                if (mode == 0)      v = alpha * a;
                else if (mode == 1) v = fmaf(alpha, a, C[ci]);
                else if (mode == 2) v = silu_f(fminf(5.f, fmaxf(-5.f, a)));
                else                v = silu_f(G[ci]) * a;
                C[ci] = v;
            }
        }
    }
#endif
}

// ============================================================
// Small helpers
// ============================================================
__global__ void transpose_kernel(const float* __restrict__ in, float* __restrict__ out,
                                 int R, int C, long sIn, long sOut)
{
    __shared__ float tile[32][33];
    in  += (long)blockIdx.z * sIn;
    out += (long)blockIdx.z * sOut;
    int r0 = blockIdx.y * 32, c0 = blockIdx.x * 32;
    int tx = threadIdx.x, ty = threadIdx.y;
#pragma unroll
    for (int i = 0; i < 32; i += 8)
        tile[ty + i][tx] = in[(long)(r0 + ty + i) * C + c0 + tx];
    __syncthreads();
#pragma unroll
    for (int i = 0; i < 32; i += 8)
        out[(long)(c0 + ty + i) * R + r0 + tx] = tile[tx][ty + i];
}

__device__ __forceinline__ float2 block_mean_var_128(float v)
{
    float s = v, s2 = v * v;
#pragma unroll
    for (int o = 16; o > 0; o >>= 1) {
        s  += __shfl_xor_sync(0xffffffffu, s,  o);
        s2 += __shfl_xor_sync(0xffffffffu, s2, o);
    }
    __shared__ float sh[8];
    int w = threadIdx.x >> 5;
    if ((threadIdx.x & 31) == 0) { sh[w] = s; sh[4 + w] = s2; }
    __syncthreads();
    s  = sh[0] + sh[1] + sh[2] + sh[3];
    s2 = sh[4] + sh[5] + sh[6] + sh[7];
    __syncthreads();
    float m = s * (1.f / 128.f);
    return make_float2(m, s2 * (1.f / 128.f) - m * m);
}

__global__ void ln_kernel(const float* __restrict__ in, float* __restrict__ out,
                          const float* __restrict__ g, const float* __restrict__ b)
{
    long row = blockIdx.x;
    int  t   = threadIdx.x;
    float v  = in[row * 128 + t];
    float2 mv = block_mean_var_128(v);
    float inv = rsqrtf(mv.y + 1e-5f);
    out[row * 128 + t] = (v - mv.x) * inv * g[t] + b[t];
}

__global__ void expert_select_kernel(const float* __restrict__ ew,
                                     const float* __restrict__ Eall,
                                     const float* __restrict__ eln_g,
                                     const float* __restrict__ eln_b,
                                     float* __restrict__ Ecomp)
{
    long m = blockIdx.x;
    int  t = threadIdx.x;
    __shared__ int sidx;
    if (t == 0) {
        int idx = -1;
        const float* w = ew + m * EE;
#pragma unroll
        for (int i = 0; i < EE; i++) if (w[i] > 0.f) idx = i;
        sidx = idx;
    }
    __syncthreads();
    int idx = sidx;
    float o = 0.f;
    if (idx >= 0) {
        float v = Eall[m * (EE * AA) + idx * AA + t];
        float2 mv = block_mean_var_128(v);
        float inv = rsqrtf(mv.y + 1e-5f);
        o = (v - mv.x) * inv * eln_g[idx * AA + t] + eln_b[idx * AA + t];
    }
    Ecomp[m * AA + t] = o;
}

// ============================================================
// Launch
// ============================================================
extern "C" void kernel_launch(void* const* d_in, const int* in_sizes, int n_in,
                              void* d_out, int out_size)
{
    const float* x       = (const float*)d_in[0];
    const float* ew      = (const float*)d_in[1];
    const float* w_up    = (const float*)d_in[2];
    const float* w_gate  = (const float*)d_in[3];
    const float* w_down  = (const float*)d_in[4];
    const float* w_pre   = (const float*)d_in[5];
    const float* w_post  = (const float*)d_in[6];
    const float* an_g    = (const float*)d_in[7];
    const float* an_b    = (const float*)d_in[8];
    const float* w_aproj = (const float*)d_in[9];
    const float* w_exp   = (const float*)d_in[10];
    const float* eln_g   = (const float*)d_in[11];
    const float* eln_b   = (const float*)d_in[12];
    const float* w_eproj = (const float*)d_in[13];
    const float* w_out   = (const float*)d_in[14];
    float* out = (float*)d_out;

    float *Yg, *Hid, *Pre, *Ain, *Post, *Aout, *AiT, *AW, *Adapt,
          *Eall, *Ecomp, *Wcomb, *W2, *Tep, *Tap;
    cudaGetSymbolAddress((void**)&Yg,    g_Yg);
    cudaGetSymbolAddress((void**)&Hid,   g_Hid);
    cudaGetSymbolAddress((void**)&Pre,   g_Pre);
    cudaGetSymbolAddress((void**)&Ain,   g_Ain);
    cudaGetSymbolAddress((void**)&Post,  g_Post);
    cudaGetSymbolAddress((void**)&Aout,  g_Aout);
    cudaGetSymbolAddress((void**)&AiT,   g_AiT);
    cudaGetSymbolAddress((void**)&AW,    g_AW);
    cudaGetSymbolAddress((void**)&Adapt, g_Adapt);
    cudaGetSymbolAddress((void**)&Eall,  g_Eall);
    cudaGetSymbolAddress((void**)&Ecomp, g_Ecomp);
    cudaGetSymbolAddress((void**)&Wcomb, g_Wcomb);
    cudaGetSymbolAddress((void**)&W2,    g_W2);
    cudaGetSymbolAddress((void**)&Tep,   g_Tep);
    cudaGetSymbolAddress((void**)&Tap,   g_Tap);

    cudaFuncSetAttribute(tc_gemm, cudaFuncAttributeMaxDynamicSharedMemorySize, TCG_SMEM);

    dim3 tb32(32, 8);

    // ---- weight-only precomputes ----
    transpose_kernel<<<dim3(AA / 32, HH / 32, 1), tb32>>>(w_eproj, Tep, HH, AA, 0, 0);
    transpose_kernel<<<dim3(AA / 32, HH / 32, 1), tb32>>>(w_aproj, Tap, HH, AA, 0, 0);
    tc_gemm<<<dim3(1, DD / 128, 1), 128, TCG_SMEM>>>(w_out, Tep, Wcomb, nullptr,
                                                     DD, AA, HH, 0, 0, 0, 1.f, 0);
    tc_gemm<<<dim3(1, DD / 128, 1), 128, TCG_SMEM>>>(w_down, Tap, W2, nullptr,
                                                     DD, AA, HH, 0, 0, 0, 1.f, 0);

    // ---- gate, then fused up*silu(gate) -> Hid ----
    tc_gemm<<<dim3(HH / 128, MM / 128, 1), 128, TCG_SMEM>>>(x, w_gate, Yg, nullptr,
                                                            MM, HH, DD, 0, 0, 0, 1.f, 0);
    tc_gemm<<<dim3(HH / 128, MM / 128, 1), 128, TCG_SMEM>>>(x, w_up, Hid, Yg,
                                                            MM, HH, DD, 0, 0, 0, 1.f, 3);

    // ---- pre / adapt_in ----
    tc_gemm<<<dim3(1, MM / 128, 1), 128, TCG_SMEM>>>(x, w_pre, Pre, nullptr,
                                                     MM, AA, DD, 0, 0, 0, 1.f, 0);
    ln_kernel<<<MM, 128>>>(Pre, Ain, an_g, an_b);

    // ---- post / adapt_out ----
    tc_gemm<<<dim3(1, MM / 128, 1), 128, TCG_SMEM>>>(Hid, w_post, Post, nullptr,
                                                     MM, AA, HH, 0, 0, 0, 1.f, 0);
    ln_kernel<<<MM, 128>>>(Post, Aout, an_g, an_b);

    // ---- adapt attention (fused silu-clip epilogue) ----
    transpose_kernel<<<dim3(AA / 32, SS / 32, BB), tb32>>>(Ain, AiT, SS, AA,
                                                           (long)SS * AA, (long)SS * AA);
    tc_gemm<<<dim3(SS / 128, SS / 128, BB), 128, TCG_SMEM>>>(Ain, Aout, AW, nullptr,
                                                             SS, SS, AA,
                                                             (long)SS * AA, (long)SS * AA,
                                                             (long)SS * SS, 1.f, 2);
    tc_gemm<<<dim3(1, SS / 128, BB), 128, TCG_SMEM>>>(AW, AiT, Adapt, nullptr,
                                                      SS, AA, SS,
                                                      (long)SS * SS, (long)AA * SS,
                                                      (long)SS * AA, 1.f, 0);

    // ---- out = Hid @ w_down^T ----
    tc_gemm<<<dim3(DD / 128, MM / 128, 1), 128, TCG_SMEM>>>(Hid, w_down, out, nullptr,
                                                            MM, DD, HH, 0, 0, 0, 1.f, 0);
    // out += 0.1 * Adapt @ W2^T
    tc_gemm<<<dim3(DD / 128, MM / 128, 1), 128, TCG_SMEM>>>(Adapt, W2, out, nullptr,
                                                            MM, DD, AA, 0, 0, 0, 0.1f, 1);

    // ---- experts ----
    tc_gemm<<<dim3(EE * AA / 128, MM / 128, 1), 128, TCG_SMEM>>>(Pre, w_exp, Eall, nullptr,
                                                                 MM, EE * AA, AA,
                                                                 0, 0, 0, 1.f, 0);
    expert_select_kernel<<<MM, 128>>>(ew, Eall, eln_g, eln_b, Ecomp);
    tc_gemm<<<dim3(DD / 128, MM / 128, 1), 128, TCG_SMEM>>>(Ecomp, Wcomb, out, nullptr,
                                                            MM, DD, AA, 0, 0, 0, 0.1f, 1);
}

// round 5
// speedup vs baseline: 3.4287x; 2.3900x over previous
#include <cuda_runtime.h>
#include <cuda_bf16.h>
#include <cstdint>

// Problem dims (fixed)
#define BB 8
#define SS 2048
#define DD 1024
#define HH 2048
#define AA 128
#define EE 8
#define MM (BB*SS)   // 16384 tokens

// tcgen05 is arch-SPECIFIC (sm_103a). Only use it in an arch-specific pass.
#if defined(__CUDA_ARCH_FEAT_SM103_ALL)
#define TCPATH 1
#endif

// -------- scratch (device globals; no allocation allowed) --------
__device__ float g_Yg[MM*HH];          // gate pre-act
__device__ float g_Hid[MM*HH];         // hidden0 = silu(gate)*up
__device__ float g_Pre[MM*AA];
__device__ float g_Ain[MM*AA];         // LN(pre)
__device__ float g_Post[MM*AA];
__device__ float g_Aout[MM*AA];        // LN(post)
__device__ float g_AiT[BB*AA*SS];      // adapt_in transposed per batch [A,S]
__device__ float g_AW[(long)BB*SS*SS]; // attention weights (post silu-clip)
__device__ float g_Adapt[MM*AA];
__device__ float g_Eall[MM*EE*AA];     // all experts' pre-LN activations
__device__ float g_Ecomp[MM*AA];       // selected+LN'd expert activation
__device__ float g_Wcomb[DD*AA];       // w_out @ w_eproj
__device__ float g_W2[DD*AA];          // w_down @ w_aproj
__device__ float g_Tep[AA*HH];         // w_eproj^T
__device__ float g_Tap[AA*HH];         // w_aproj^T

// ============================================================
// common helpers
// ============================================================
__device__ __forceinline__ float silu_f(float v) {
    return v * __frcp_rn(1.f + __expf(-v));
}

__device__ __forceinline__ uint32_t f2tf32(float f) {
    uint32_t u;
    asm("cvt.rna.tf32.f32 %0, %1;" : "=r"(u) : "f"(f));
    return u;
}

#ifdef TCPATH
// ============================================================
// tcgen05 helpers (sm_103a-specific pass only)
// ============================================================
__device__ __forceinline__ uint32_t smem_u32(const void* p) {
    uint32_t a;
    asm("{ .reg .u64 t; cvta.to.shared.u64 t, %1; cvt.u32.u64 %0, t; }"
        : "=r"(a) : "l"(p));
    return a;
}

__device__ __forceinline__ uint32_t elect1() {
    uint32_t p;
    asm volatile("{\n\t.reg .pred p;\n\telect.sync _|p, 0xFFFFFFFF;\n\t"
                 "selp.b32 %0, 1, 0, p;\n\t}" : "=r"(p));
    return p;
}

#define MBAR_INIT(addr, cnt) \
    asm volatile("mbarrier.init.shared.b64 [%0], %1;" :: "r"(addr), "r"(cnt) : "memory")

__device__ __forceinline__ void mbar_wait(uint32_t mbar, uint32_t parity) {
    uint32_t done;
    asm volatile("{\n\t.reg .pred p;\n\t"
                 "mbarrier.try_wait.parity.acquire.cta.shared::cta.b64 p, [%1], %2;\n\t"
                 "selp.b32 %0, 1, 0, p;\n\t}"
                 : "=r"(done) : "r"(mbar), "r"(parity) : "memory");
    while (!done) {
        asm volatile("{\n\t.reg .pred p;\n\t"
                     "mbarrier.try_wait.parity.acquire.cta.shared::cta.b64 p, [%1], %2, 0x989680;\n\t"
                     "selp.b32 %0, 1, 0, p;\n\t}"
                     : "=r"(done) : "r"(mbar), "r"(parity) : "memory");
    }
}

__device__ __forceinline__ void mma_tf32(uint32_t d, uint64_t da, uint64_t db,
                                         uint32_t idesc, uint32_t en) {
    asm volatile(
        "{\n\t.reg .pred p;\n\tsetp.ne.u32 p, %4, 0;\n\t"
        "tcgen05.mma.cta_group::1.kind::tf32 [%0], %1, %2, %3, {%5, %5, %5, %5}, p;\n\t}"
        :: "r"(d), "l"(da), "l"(db), "r"(idesc), "r"(en), "r"(0u)
        : "memory");
}

#define TC_COMMIT(mbar) \
    asm volatile("tcgen05.commit.cta_group::1.mbarrier::arrive::one.shared::cluster.b64 [%0];" \
                 :: "r"(mbar) : "memory")

#define LDTM_X32(r, addr) \
    asm volatile("tcgen05.ld.sync.aligned.32x32b.x32.b32 " \
        "{%0,%1,%2,%3,%4,%5,%6,%7,%8,%9,%10,%11,%12,%13,%14,%15," \
        "%16,%17,%18,%19,%20,%21,%22,%23,%24,%25,%26,%27,%28,%29,%30,%31}, [%32];" \
        : "=r"((r)[0]),  "=r"((r)[1]),  "=r"((r)[2]),  "=r"((r)[3]), \
          "=r"((r)[4]),  "=r"((r)[5]),  "=r"((r)[6]),  "=r"((r)[7]), \
          "=r"((r)[8]),  "=r"((r)[9]),  "=r"((r)[10]), "=r"((r)[11]), \
          "=r"((r)[12]), "=r"((r)[13]), "=r"((r)[14]), "=r"((r)[15]), \
          "=r"((r)[16]), "=r"((r)[17]), "=r"((r)[18]), "=r"((r)[19]), \
          "=r"((r)[20]), "=r"((r)[21]), "=r"((r)[22]), "=r"((r)[23]), \
          "=r"((r)[24]), "=r"((r)[25]), "=r"((r)[26]), "=r"((r)[27]), \
          "=r"((r)[28]), "=r"((r)[29]), "=r"((r)[30]), "=r"((r)[31]) \
        : "r"(addr))

static __device__ __forceinline__ uint64_t make_desc(uint32_t addr) {
    const uint64_t base = (2ULL << 61) | (1ULL << 46) | (64ULL << 32) | (1ULL << 16);
    return base | ((uint64_t)(addr >> 4) & 0x3FFF);
}

// idesc: dtype=F32(1<<4), atype=btype=TF32(2), N=128 ((N/8)<<17), M=128 ((M/16)<<24)
#define IDESC_TF32 ((1u << 4) | (2u << 7) | (2u << 10) | (16u << 17) | (8u << 24))
#endif  // TCPATH

// ============================================================
// tensor GEMM-NT:  C[M,N] (op)= alpha * A[M,K] * B[N,K]^T
// row-major, K contiguous in both. Tile 128x128, K-chunk 32, 256 threads.
// Requires M%128==0, N%128==0, (K/ksplit)%32==0, K/ksplit>=128.
// mode 0: C = alpha*acc
// mode 1: C += alpha*acc            (non-atomic RMW)
// mode 2: C = silu(clip(acc,-5,5))
// mode 3: C = silu(G[idx]) * acc    (fused SwiGLU)
// mode 4: atomicAdd(C, alpha*acc)   (split-K)
// grid = (N/128, M/128, batch*ksplit)
// ============================================================
#define TCG_SMEM (2048 + 2 * 32768)   // 67584

__global__ __launch_bounds__(256)
void tc_gemm(const float* __restrict__ A, const float* __restrict__ B,
             float* __restrict__ C, const float* __restrict__ G,
             int M, int N, int K, long sA, long sB, long sC,
             float alpha, int mode, int ksplit)
{
    extern __shared__ char smem[];
    const int tid  = threadIdx.x;
    const int wid  = tid >> 5;
    const int lane = tid & 31;

    int Kc;
    {
        int bz = blockIdx.z;
        long b = bz / ksplit;
        int ik = bz - (int)b * ksplit;
        Kc = K / ksplit;
        // NOTE: K stays the ROW STRIDE; split only offsets the k-window.
        A += b * sA + (long)ik * Kc;
        B += b * sB + (long)ik * Kc;
        C += b * sC;
        if (mode == 3) G += b * sC;
    }
    const int m0 = blockIdx.y * 128, n0 = blockIdx.x * 128;
    const float* Ap = A + (long)m0 * K;
    const float* Bp = B + (long)n0 * K;
    const int nch = Kc >> 5;

#ifdef TCPATH
    // -------------------- tcgen05 path --------------------
    uint32_t sbase = smem_u32(smem);
    const uint32_t TM_PTR = sbase;
    const uint32_t MB0 = sbase + 16;
    const uint32_t MB1 = sbase + 24;
    uint32_t data0 = (sbase + 1024 + 1023) & ~1023u;
    char* dptr = smem + (data0 - sbase);

    if (wid == 0) {
        asm volatile("tcgen05.alloc.cta_group::1.sync.aligned.shared::cta.b32 [%0], %1;"
                     :: "r"(TM_PTR), "r"(128u) : "memory");
        asm volatile("tcgen05.relinquish_alloc_permit.cta_group::1.sync.aligned;");
    }
    if (tid == 0) { MBAR_INIT(MB0, 1); MBAR_INIT(MB1, 1); }
    __syncthreads();
    uint32_t tmem;
    asm volatile("ld.shared.b32 %0, [%1];" : "=r"(tmem) : "r"(TM_PTR));

    int ph0 = 0, ph1 = 0;
    for (int i = 0; i < nch; i++) {
        const int buf = i & 1;
        const uint32_t offS = buf * 32768u;      // A 16KB + B 16KB per stage
        if (i >= 2) {
            if (buf == 0) { mbar_wait(MB0, ph0); ph0 ^= 1; }
            else          { mbar_wait(MB1, ph1); ph1 ^= 1; }
        }
        const int k0 = i << 5;
#pragma unroll
        for (int it = 0; it < 8; it++) {
            int idx = it * 256 + tid;
            int r = idx >> 3, q = idx & 7;   // r: 0..255 (A rows 0-127, B rows 128-255)
            const float* src = (r < 128) ? (Ap + (long)r * K) : (Bp + (long)(r - 128) * K);
            float4 v = *(const float4*)(src + k0 + q * 4);
            uint4 u = make_uint4(f2tf32(v.x), f2tf32(v.y), f2tf32(v.z), f2tf32(v.w));
            uint32_t off = (uint32_t)(r * 128 + q * 16);
            uint32_t sw = off ^ ((off >> 3) & 0x70u);
            *(uint4*)(dptr + offS + sw) = u;
        }
        asm volatile("fence.proxy.async.shared::cta;" ::: "memory");
        __syncthreads();
        if (wid == 0 && elect1()) {
            uint64_t da = make_desc(data0 + offS);
            uint64_t db = make_desc(data0 + offS + 16384u);
#pragma unroll
            for (int ks = 0; ks < 4; ks++)
                mma_tf32(tmem, da + ks * 2, db + ks * 2, IDESC_TF32,
                         (i > 0 || ks > 0) ? 1u : 0u);
            TC_COMMIT(buf == 0 ? MB0 : MB1);
        }
    }
    mbar_wait(MB0, ph0);
    mbar_wait(MB1, ph1);
    asm volatile("tcgen05.fence::after_thread_sync;" ::: "memory");

    // ---- epilogue: warps 0-3 handle the 128x128 tile ----
    if (wid < 4) {
        float* Crow = C + (long)(m0 + wid * 32 + lane) * N + n0;
        const float* Grow = (mode == 3)
            ? (G + (long)(m0 + wid * 32 + lane) * N + n0) : nullptr;
#pragma unroll
        for (int cb = 0; cb < 128; cb += 32) {
            uint32_t r[32];
            LDTM_X32(r, tmem + cb);
            asm volatile("tcgen05.wait::ld.sync.aligned;" ::: "memory");
            if (mode == 4) {
#pragma unroll
                for (int j = 0; j < 32; j++)
                    atomicAdd(Crow + cb + j, alpha * __uint_as_float(r[j]));
            } else {
#pragma unroll
                for (int j = 0; j < 32; j += 4) {
                    float4 v;
                    v.x = __uint_as_float(r[j + 0]);
                    v.y = __uint_as_float(r[j + 1]);
                    v.z = __uint_as_float(r[j + 2]);
                    v.w = __uint_as_float(r[j + 3]);
                    if (mode == 0) {
                        v.x *= alpha; v.y *= alpha; v.z *= alpha; v.w *= alpha;
                    } else if (mode == 1) {
                        float4 c = *(const float4*)(Crow + cb + j);
                        v.x = fmaf(alpha, v.x, c.x); v.y = fmaf(alpha, v.y, c.y);
                        v.z = fmaf(alpha, v.z, c.z); v.w = fmaf(alpha, v.w, c.w);
                    } else if (mode == 2) {
                        v.x = silu_f(fminf(5.f, fmaxf(-5.f, v.x)));
                        v.y = silu_f(fminf(5.f, fmaxf(-5.f, v.y)));
                        v.z = silu_f(fminf(5.f, fmaxf(-5.f, v.z)));
                        v.w = silu_f(fminf(5.f, fmaxf(-5.f, v.w)));
                    } else {
                        float4 g = *(const float4*)(Grow + cb + j);
                        v.x *= silu_f(g.x); v.y *= silu_f(g.y);
                        v.z *= silu_f(g.z); v.w *= silu_f(g.w);
                    }
                    *(float4*)(Crow + cb + j) = v;
                }
            }
        }
    }
    asm volatile("tcgen05.fence::before_thread_sync;" ::: "memory");
    __syncthreads();
    if (wid == 0) {
        asm volatile("tcgen05.dealloc.cta_group::1.sync.aligned.b32 %0, %1;"
                     :: "r"(tmem), "r"(128u));
    }
#else
    // -------------------- mma.sync tf32 fallback (compile-only safety net) --------------------
    // 8 warps 2x4; warp tile 64x32; m16n8k8 tf32.
    uint32_t* As = (uint32_t*)smem;          // [128][36] A then [128][36] B
    uint32_t* Bs = As + 128 * 36;

    const int warpM = wid >> 2, warpN = wid & 3;
    const int g  = lane >> 2;
    const int tk = lane & 3;

    float acc[4][4][4];
#pragma unroll
    for (int mt = 0; mt < 4; mt++)
#pragma unroll
        for (int nt = 0; nt < 4; nt++)
#pragma unroll
            for (int j = 0; j < 4; j++) acc[mt][nt][j] = 0.f;

    for (int i = 0; i < nch; i++) {
        __syncthreads();
        const int k0 = i << 5;
#pragma unroll
        for (int it = 0; it < 8; it++) {
            int idx = it * 256 + tid;
            int r = idx >> 3, q = idx & 7;
            const float* src = (r < 128) ? (Ap + (long)r * K) : (Bp + (long)(r - 128) * K);
            float4 v = *(const float4*)(src + k0 + q * 4);
            uint4 u = make_uint4(f2tf32(v.x), f2tf32(v.y), f2tf32(v.z), f2tf32(v.w));
            *(uint4*)(As + r * 36 + q * 4) = u;
        }
        __syncthreads();
#pragma unroll
        for (int kk = 0; kk < 4; kk++) {
            uint32_t af[4][4];
#pragma unroll
            for (int mt = 0; mt < 4; mt++) {
                int ra = warpM * 64 + mt * 16 + g;
                af[mt][0] = As[ra * 36 + kk * 8 + tk];
                af[mt][1] = As[(ra + 8) * 36 + kk * 8 + tk];
                af[mt][2] = As[ra * 36 + kk * 8 + tk + 4];
                af[mt][3] = As[(ra + 8) * 36 + kk * 8 + tk + 4];
            }
            uint32_t bf[4][2];
#pragma unroll
            for (int nt = 0; nt < 4; nt++) {
                int rb = warpN * 32 + nt * 8 + g;
                bf[nt][0] = Bs[rb * 36 + kk * 8 + tk];
                bf[nt][1] = Bs[rb * 36 + kk * 8 + tk + 4];
            }
#pragma unroll
            for (int mt = 0; mt < 4; mt++)
#pragma unroll
                for (int nt = 0; nt < 4; nt++) {
                    asm volatile(
                        "mma.sync.aligned.m16n8k8.row.col.f32.tf32.tf32.f32 "
                        "{%0,%1,%2,%3}, {%4,%5,%6,%7}, {%8,%9}, {%0,%1,%2,%3};"
                        : "+f"(acc[mt][nt][0]), "+f"(acc[mt][nt][1]),
                          "+f"(acc[mt][nt][2]), "+f"(acc[mt][nt][3])
                        : "r"(af[mt][0]), "r"(af[mt][1]), "r"(af[mt][2]), "r"(af[mt][3]),
                          "r"(bf[nt][0]), "r"(bf[nt][1]));
                }
        }
    }
#pragma unroll
    for (int mt = 0; mt < 4; mt++)
#pragma unroll
        for (int nt = 0; nt < 4; nt++)
#pragma unroll
            for (int j = 0; j < 4; j++) {
                int row = m0 + warpM * 64 + mt * 16 + g + ((j >= 2) ? 8 : 0);
                int col = n0 + warpN * 32 + nt * 8 + tk * 2 + (j & 1);
                long ci = (long)row * N + col;
                float a = acc[mt][nt][j];
                if (mode == 4)      atomicAdd(C + ci, alpha * a);
                else if (mode == 0) C[ci] = alpha * a;
                else if (mode == 1) C[ci] = fmaf(alpha, a, C[ci]);
                else if (mode == 2) C[ci] = silu_f(fminf(5.f, fmaxf(-5.f, a)));
                else                C[ci] = silu_f(G[ci]) * a;
            }
#endif
}

// ============================================================
// Small helpers
// ============================================================
__global__ void zero_kernel(float* p, long n)
{
    long i = (long)blockIdx.x * blockDim.x + threadIdx.x;
    long stride = (long)gridDim.x * blockDim.x;
    for (; i < n; i += stride) p[i] = 0.f;
}

__global__ void transpose_kernel(const float* __restrict__ in, float* __restrict__ out,
                                 int R, int C, long sIn, long sOut)
{
    __shared__ float tile[32][33];
    in  += (long)blockIdx.z * sIn;
    out += (long)blockIdx.z * sOut;
    int r0 = blockIdx.y * 32, c0 = blockIdx.x * 32;
    int tx = threadIdx.x, ty = threadIdx.y;
#pragma unroll
    for (int i = 0; i < 32; i += 8)
        tile[ty + i][tx] = in[(long)(r0 + ty + i) * C + c0 + tx];
    __syncthreads();
#pragma unroll
    for (int i = 0; i < 32; i += 8)
        out[(long)(c0 + ty + i) * R + r0 + tx] = tile[tx][ty + i];
}

__device__ __forceinline__ float2 block_mean_var_128(float v)
{
    float s = v, s2 = v * v;
#pragma unroll
    for (int o = 16; o > 0; o >>= 1) {
        s  += __shfl_xor_sync(0xffffffffu, s,  o);
        s2 += __shfl_xor_sync(0xffffffffu, s2, o);
    }
    __shared__ float sh[8];
    int w = threadIdx.x >> 5;
    if ((threadIdx.x & 31) == 0) { sh[w] = s; sh[4 + w] = s2; }
    __syncthreads();
    s  = sh[0] + sh[1] + sh[2] + sh[3];
    s2 = sh[4] + sh[5] + sh[6] + sh[7];
    __syncthreads();
    float m = s * (1.f / 128.f);
    return make_float2(m, s2 * (1.f / 128.f) - m * m);
}

__global__ void ln_kernel(const float* __restrict__ in, float* __restrict__ out,
                          const float* __restrict__ g, const float* __restrict__ b)
{
    long row = blockIdx.x;
    int  t   = threadIdx.x;
    float v  = in[row * 128 + t];
    float2 mv = block_mean_var_128(v);
    float inv = rsqrtf(mv.y + 1e-5f);
    out[row * 128 + t] = (v - mv.x) * inv * g[t] + b[t];
}

__global__ void expert_select_kernel(const float* __restrict__ ew,
                                     const float* __restrict__ Eall,
                                     const float* __restrict__ eln_g,
                                     const float* __restrict__ eln_b,
                                     float* __restrict__ Ecomp)
{
    long m = blockIdx.x;
    int  t = threadIdx.x;
    __shared__ int sidx;
    if (t == 0) {
        int idx = -1;
        const float* w = ew + m * EE;
#pragma unroll
        for (int i = 0; i < EE; i++) if (w[i] > 0.f) idx = i;
        sidx = idx;
    }
    __syncthreads();
    int idx = sidx;
    float o = 0.f;
    if (idx >= 0) {
        float v = Eall[m * (EE * AA) + idx * AA + t];
        float2 mv = block_mean_var_128(v);
        float inv = rsqrtf(mv.y + 1e-5f);
        o = (v - mv.x) * inv * eln_g[idx * AA + t] + eln_b[idx * AA + t];
    }
    Ecomp[m * AA + t] = o;
}

// ============================================================
// Launch
// ============================================================
extern "C" void kernel_launch(void* const* d_in, const int* in_sizes, int n_in,
                              void* d_out, int out_size)
{
    const float* x       = (const float*)d_in[0];
    const float* ew      = (const float*)d_in[1];
    const float* w_up    = (const float*)d_in[2];
    const float* w_gate  = (const float*)d_in[3];
    const float* w_down  = (const float*)d_in[4];
    const float* w_pre   = (const float*)d_in[5];
    const float* w_post  = (const float*)d_in[6];
    const float* an_g    = (const float*)d_in[7];
    const float* an_b    = (const float*)d_in[8];
    const float* w_aproj = (const float*)d_in[9];
    const float* w_exp   = (const float*)d_in[10];
    const float* eln_g   = (const float*)d_in[11];
    const float* eln_b   = (const float*)d_in[12];
    const float* w_eproj = (const float*)d_in[13];
    const float* w_out   = (const float*)d_in[14];
    float* out = (float*)d_out;

    float *Yg, *Hid, *Pre, *Ain, *Post, *Aout, *AiT, *AW, *Adapt,
          *Eall, *Ecomp, *Wcomb, *W2, *Tep, *Tap;
    cudaGetSymbolAddress((void**)&Yg,    g_Yg);
    cudaGetSymbolAddress((void**)&Hid,   g_Hid);
    cudaGetSymbolAddress((void**)&Pre,   g_Pre);
    cudaGetSymbolAddress((void**)&Ain,   g_Ain);
    cudaGetSymbolAddress((void**)&Post,  g_Post);
    cudaGetSymbolAddress((void**)&Aout,  g_Aout);
    cudaGetSymbolAddress((void**)&AiT,   g_AiT);
    cudaGetSymbolAddress((void**)&AW,    g_AW);
    cudaGetSymbolAddress((void**)&Adapt, g_Adapt);
    cudaGetSymbolAddress((void**)&Eall,  g_Eall);
    cudaGetSymbolAddress((void**)&Ecomp, g_Ecomp);
    cudaGetSymbolAddress((void**)&Wcomb, g_Wcomb);
    cudaGetSymbolAddress((void**)&W2,    g_W2);
    cudaGetSymbolAddress((void**)&Tep,   g_Tep);
    cudaGetSymbolAddress((void**)&Tap,   g_Tap);

    cudaFuncSetAttribute(tc_gemm, cudaFuncAttributeMaxDynamicSharedMemorySize, TCG_SMEM);

    dim3 tb32(32, 8);

    // ---- zero split-K atomic targets ----
    zero_kernel<<<64,  256>>>(Wcomb, (long)DD * AA);
    zero_kernel<<<64,  256>>>(W2,    (long)DD * AA);
    zero_kernel<<<256, 256>>>(Pre,   (long)MM * AA);
    zero_kernel<<<256, 256>>>(Post,  (long)MM * AA);
    zero_kernel<<<256, 256>>>(Adapt, (long)MM * AA);

    // ---- weight-only precomputes (split-K 16, atomic) ----
    transpose_kernel<<<dim3(AA / 32, HH / 32, 1), tb32>>>(w_eproj, Tep, HH, AA, 0, 0);
    transpose_kernel<<<dim3(AA / 32, HH / 32, 1), tb32>>>(w_aproj, Tap, HH, AA, 0, 0);
    tc_gemm<<<dim3(1, DD / 128, 16), 256, TCG_SMEM>>>(w_out, Tep, Wcomb, nullptr,
                                                      DD, AA, HH, 0, 0, 0, 1.f, 4, 16);
    tc_gemm<<<dim3(1, DD / 128, 16), 256, TCG_SMEM>>>(w_down, Tap, W2, nullptr,
                                                      DD, AA, HH, 0, 0, 0, 1.f, 4, 16);

    // ---- gate, then fused up*silu(gate) -> Hid ----
    tc_gemm<<<dim3(HH / 128, MM / 128, 1), 256, TCG_SMEM>>>(x, w_gate, Yg, nullptr,
                                                            MM, HH, DD, 0, 0, 0, 1.f, 0, 1);
    tc_gemm<<<dim3(HH / 128, MM / 128, 1), 256, TCG_SMEM>>>(x, w_up, Hid, Yg,
                                                            MM, HH, DD, 0, 0, 0, 1.f, 3, 1);

    // ---- pre / adapt_in (split-K 2 for occupancy) ----
    tc_gemm<<<dim3(1, MM / 128, 2), 256, TCG_SMEM>>>(x, w_pre, Pre, nullptr,
                                                     MM, AA, DD, 0, 0, 0, 1.f, 4, 2);
    ln_kernel<<<MM, 128>>>(Pre, Ain, an_g, an_b);

    // ---- post / adapt_out (split-K 2) ----
    tc_gemm<<<dim3(1, MM / 128, 2), 256, TCG_SMEM>>>(Hid, w_post, Post, nullptr,
                                                     MM, AA, HH, 0, 0, 0, 1.f, 4, 2);
    ln_kernel<<<MM, 128>>>(Post, Aout, an_g, an_b);

    // ---- adapt attention (fused silu-clip epilogue) ----
    transpose_kernel<<<dim3(AA / 32, SS / 32, BB), tb32>>>(Ain, AiT, SS, AA,
                                                           (long)SS * AA, (long)SS * AA);
    tc_gemm<<<dim3(SS / 128, SS / 128, BB), 256, TCG_SMEM>>>(Ain, Aout, AW, nullptr,
                                                             SS, SS, AA,
                                                             (long)SS * AA, (long)SS * AA,
                                                             (long)SS * SS, 1.f, 2, 1);
    // Adapt[b] = AW[b] @ AiT^T (batch 8, split-K 2, atomic)
    tc_gemm<<<dim3(1, SS / 128, BB * 2), 256, TCG_SMEM>>>(AW, AiT, Adapt, nullptr,
                                                          SS, AA, SS,
                                                          (long)SS * SS, (long)AA * SS,
                                                          (long)SS * AA, 1.f, 4, 2);

    // ---- out = Hid @ w_down^T ----
    tc_gemm<<<dim3(DD / 128, MM / 128, 1), 256, TCG_SMEM>>>(Hid, w_down, out, nullptr,
                                                            MM, DD, HH, 0, 0, 0, 1.f, 0, 1);
    // out += 0.1 * Adapt @ W2^T
    tc_gemm<<<dim3(DD / 128, MM / 128, 1), 256, TCG_SMEM>>>(Adapt, W2, out, nullptr,
                                                            MM, DD, AA, 0, 0, 0, 0.1f, 1, 1);

    // ---- experts ----
    tc_gemm<<<dim3(EE * AA / 128, MM / 128, 1), 256, TCG_SMEM>>>(Pre, w_exp, Eall, nullptr,
                                                                 MM, EE * AA, AA,
                                                                 0, 0, 0, 1.f, 0, 1);
    expert_select_kernel<<<MM, 128>>>(ew, Eall, eln_g, eln_b, Ecomp);
    // out += 0.1 * Ecomp @ Wcomb^T
    tc_gemm<<<dim3(DD / 128, MM / 128, 1), 256, TCG_SMEM>>>(Ecomp, Wcomb, out, nullptr,
                                                            MM, DD, AA, 0, 0, 0, 0.1f, 1, 1);
}

// round 6
// speedup vs baseline: 5.1860x; 1.5125x over previous
#include <cuda_runtime.h>
#include <cuda_bf16.h>
#include <cstdint>

// Problem dims (fixed)
#define BB 8
#define SS 2048
#define DD 1024
#define HH 2048
#define AA 128
#define EE 8
#define MM (BB*SS)   // 16384 tokens

// tcgen05 is arch-SPECIFIC (sm_103a). Only use it in an arch-specific pass.
#if defined(__CUDA_ARCH_FEAT_SM103_ALL)
#define TCPATH 1
#endif

// -------- scratch (device globals; no allocation allowed) --------
__device__ float g_Yg[MM*HH];          // gate pre-act (exact fp32)
__device__ float g_Hid[MM*HH];         // hidden0 = silu(gate)*up (tf32-rounded)
__device__ float g_Pre[MM*AA];         // exact (atomic target)
__device__ float g_PreR[MM*AA];        // rounded copy for GEMM A
__device__ float g_Ain[MM*AA];         // LN(pre), rounded
__device__ float g_Post[MM*AA];        // exact (atomic target)
__device__ float g_Aout[MM*AA];        // LN(post), rounded
__device__ float g_AiT[BB*AA*SS];      // adapt_in transposed per batch [A,S], rounded
__device__ float g_AW[(long)BB*SS*SS]; // attention weights (silu-clip), rounded
__device__ float g_Adapt[MM*AA];       // exact (atomic target)
__device__ float g_AdaptR[MM*AA];      // rounded
__device__ float g_Eall[MM*EE*AA];     // experts' pre-LN activations (exact)
__device__ float g_Ecomp[MM*AA];       // selected+LN'd expert act, rounded
__device__ float g_Wcomb[DD*AA];       // w_out @ w_eproj (exact, atomic)
__device__ float g_WcombR[DD*AA];      // rounded
__device__ float g_W2[DD*AA];          // w_down @ w_aproj (exact, atomic)
__device__ float g_W2R[DD*AA];         // rounded
__device__ float g_Tep[AA*HH];         // w_eproj^T, rounded
__device__ float g_Tap[AA*HH];         // w_aproj^T, rounded
// rounded raw inputs
__device__ float g_xR[MM*DD];
__device__ float g_WgR[HH*DD];
__device__ float g_WuR[HH*DD];
__device__ float g_WdR[DD*HH];
__device__ float g_WoutR[DD*HH];
__device__ float g_WpreR[AA*DD];
__device__ float g_WpostR[AA*HH];
__device__ float g_WexpR[EE*AA*AA];

// ============================================================
// common helpers
// ============================================================
__device__ __forceinline__ float silu_f(float v) {
    return v * __frcp_rn(1.f + __expf(-v));
}

__device__ __forceinline__ uint32_t f2tf32(float f) {
    uint32_t u;
    asm("cvt.rna.tf32.f32 %0, %1;" : "=r"(u) : "f"(f));
    return u;
}
__device__ __forceinline__ float rndf(float f) {
    return __uint_as_float(f2tf32(f));
}

#ifdef TCPATH
// ============================================================
// tcgen05 helpers (sm_103a-specific pass only)
// ============================================================
__device__ __forceinline__ uint32_t smem_u32(const void* p) {
    uint32_t a;
    asm("{ .reg .u64 t; cvta.to.shared.u64 t, %1; cvt.u32.u64 %0, t; }"
        : "=r"(a) : "l"(p));
    return a;
}

__device__ __forceinline__ uint32_t elect1() {
    uint32_t p;
    asm volatile("{\n\t.reg .pred p;\n\telect.sync _|p, 0xFFFFFFFF;\n\t"
                 "selp.b32 %0, 1, 0, p;\n\t}" : "=r"(p));
    return p;
}

#define MBAR_INIT(addr, cnt) \
    asm volatile("mbarrier.init.shared.b64 [%0], %1;" :: "r"(addr), "r"(cnt) : "memory")

__device__ __forceinline__ void mbar_wait(uint32_t mbar, uint32_t parity) {
    uint32_t done;
    asm volatile("{\n\t.reg .pred p;\n\t"
                 "mbarrier.try_wait.parity.acquire.cta.shared::cta.b64 p, [%1], %2;\n\t"
                 "selp.b32 %0, 1, 0, p;\n\t}"
                 : "=r"(done) : "r"(mbar), "r"(parity) : "memory");
    while (!done) {
        asm volatile("{\n\t.reg .pred p;\n\t"
                     "mbarrier.try_wait.parity.acquire.cta.shared::cta.b64 p, [%1], %2, 0x989680;\n\t"
                     "selp.b32 %0, 1, 0, p;\n\t}"
                     : "=r"(done) : "r"(mbar), "r"(parity) : "memory");
    }
}

__device__ __forceinline__ void mma_tf32(uint32_t d, uint64_t da, uint64_t db,
                                         uint32_t idesc, uint32_t en) {
    asm volatile(
        "{\n\t.reg .pred p;\n\tsetp.ne.u32 p, %4, 0;\n\t"
        "tcgen05.mma.cta_group::1.kind::tf32 [%0], %1, %2, %3, {%5, %5, %5, %5}, p;\n\t}"
        :: "r"(d), "l"(da), "l"(db), "r"(idesc), "r"(en), "r"(0u)
        : "memory");
}

#define TC_COMMIT(mbar) \
    asm volatile("tcgen05.commit.cta_group::1.mbarrier::arrive::one.shared::cluster.b64 [%0];" \
                 :: "r"(mbar) : "memory")

#define LDTM_X32(r, addr) \
    asm volatile("tcgen05.ld.sync.aligned.32x32b.x32.b32 " \
        "{%0,%1,%2,%3,%4,%5,%6,%7,%8,%9,%10,%11,%12,%13,%14,%15," \
        "%16,%17,%18,%19,%20,%21,%22,%23,%24,%25,%26,%27,%28,%29,%30,%31}, [%32];" \
        : "=r"((r)[0]),  "=r"((r)[1]),  "=r"((r)[2]),  "=r"((r)[3]), \
          "=r"((r)[4]),  "=r"((r)[5]),  "=r"((r)[6]),  "=r"((r)[7]), \
          "=r"((r)[8]),  "=r"((r)[9]),  "=r"((r)[10]), "=r"((r)[11]), \
          "=r"((r)[12]), "=r"((r)[13]), "=r"((r)[14]), "=r"((r)[15]), \
          "=r"((r)[16]), "=r"((r)[17]), "=r"((r)[18]), "=r"((r)[19]), \
          "=r"((r)[20]), "=r"((r)[21]), "=r"((r)[22]), "=r"((r)[23]), \
          "=r"((r)[24]), "=r"((r)[25]), "=r"((r)[26]), "=r"((r)[27]), \
          "=r"((r)[28]), "=r"((r)[29]), "=r"((r)[30]), "=r"((r)[31]) \
        : "r"(addr))

static __device__ __forceinline__ uint64_t make_desc(uint32_t addr) {
    const uint64_t base = (2ULL << 61) | (1ULL << 46) | (64ULL << 32) | (1ULL << 16);
    return base | ((uint64_t)(addr >> 4) & 0x3FFF);
}

// idesc: dtype=F32(1<<4), atype=btype=TF32(2), N=128 ((N/8)<<17), M=128 ((M/16)<<24)
#define IDESC_TF32 ((1u << 4) | (2u << 7) | (2u << 10) | (16u << 17) | (8u << 24))
#endif  // TCPATH

// ============================================================
// tensor GEMM-NT:  C[M,N] (op)= alpha * A[M,K] * B[N,K]^T
// row-major, K contiguous. Tile 128x128, K-chunk 32, 256 threads,
// 3-stage cp.async pipeline. A and B MUST be tf32-pre-rounded.
// Requires M%128==0, N%128==0, (K/ksplit)%32==0, K/ksplit>=128.
// mode 0: C = alpha*acc
// mode 1: C += alpha*acc            (non-atomic RMW)
// mode 2: C = silu(clip(acc,-5,5))
// mode 3: C = silu(G[idx]) * acc    (fused SwiGLU)
// mode 4: atomicAdd(C, alpha*acc)   (split-K)
// rnd != 0: tf32-round stores (modes 0/2/3)
// grid = (N/128, M/128, batch*ksplit)
// ============================================================
#define TCG_SMEM (2048 + 3 * 32768)   // 100352

__global__ __launch_bounds__(256)
void tc_gemm(const float* __restrict__ A, const float* __restrict__ B,
             float* __restrict__ C, const float* __restrict__ G,
             int M, int N, int K, long sA, long sB, long sC,
             float alpha, int mode, int ksplit, int rnd)
{
    extern __shared__ char smem[];
    const int tid  = threadIdx.x;
    const int wid  = tid >> 5;
    const int lane = tid & 31;

    int Kc;
    {
        int bz = blockIdx.z;
        long b = bz / ksplit;
        int ik = bz - (int)b * ksplit;
        Kc = K / ksplit;
        // K stays the ROW STRIDE; split only offsets the k-window.
        A += b * sA + (long)ik * Kc;
        B += b * sB + (long)ik * Kc;
        C += b * sC;
        if (mode == 3) G += b * sC;
    }
    const int m0 = blockIdx.y * 128, n0 = blockIdx.x * 128;
    const float* Ap = A + (long)m0 * K;
    const float* Bp = B + (long)n0 * K;
    const int nch = Kc >> 5;   // >= 4 for all our shapes

#ifdef TCPATH
    // -------------------- tcgen05 + cp.async path --------------------
    uint32_t sbase = smem_u32(smem);
    const uint32_t TM_PTR = sbase;
    const uint32_t MB0 = sbase + 16;
    const uint32_t MB1 = sbase + 24;
    const uint32_t MB2 = sbase + 32;
    uint32_t data0 = (sbase + 1024 + 1023) & ~1023u;

    if (wid == 0) {
        asm volatile("tcgen05.alloc.cta_group::1.sync.aligned.shared::cta.b32 [%0], %1;"
                     :: "r"(TM_PTR), "r"(128u) : "memory");
        asm volatile("tcgen05.relinquish_alloc_permit.cta_group::1.sync.aligned;");
    }
    if (tid == 0) { MBAR_INIT(MB0, 1); MBAR_INIT(MB1, 1); MBAR_INIT(MB2, 1); }
    __syncthreads();
    uint32_t tmem;
    asm volatile("ld.shared.b32 %0, [%1];" : "=r"(tmem) : "r"(TM_PTR));

#define ISSUE_CP(c, b) do {                                                  \
        const int k0_ = (c) << 5;                                            \
        const uint32_t so_ = (uint32_t)(b) * 32768u;                         \
        _Pragma("unroll")                                                    \
        for (int it_ = 0; it_ < 8; it_++) {                                  \
            int idx_ = it_ * 256 + tid;                                      \
            int r_ = idx_ >> 3, q_ = idx_ & 7;                               \
            const float* src_ = (r_ < 128)                                   \
                ? (Ap + (long)r_ * K + k0_ + q_ * 4)                         \
                : (Bp + (long)(r_ - 128) * K + k0_ + q_ * 4);                \
            uint32_t off_ = (uint32_t)(r_ * 128 + q_ * 16);                  \
            uint32_t sw_ = off_ ^ ((off_ >> 3) & 0x70u);                     \
            asm volatile("cp.async.cg.shared.global [%0], [%1], 16;"         \
                :: "r"(data0 + so_ + sw_), "l"(src_) : "memory");            \
        }                                                                    \
        asm volatile("cp.async.commit_group;" ::: "memory");                 \
    } while (0)

    int ph0 = 0, ph1 = 0, ph2 = 0;
    // prologue: chunks 0,1 into buffers 0,1
    ISSUE_CP(0, 0);
    ISSUE_CP(1, 1);

    for (int i = 0; i < nch; i++) {
        const int ip2 = i + 2;
        if (ip2 < nch) {
            const int b = ip2 % 3;
            if (i >= 1) {  // buffer b holds chunk i-1; its MMA must be done
                if (b == 0)      { mbar_wait(MB0, ph0); ph0 ^= 1; }
                else if (b == 1) { mbar_wait(MB1, ph1); ph1 ^= 1; }
                else             { mbar_wait(MB2, ph2); ph2 ^= 1; }
            }
            ISSUE_CP(ip2, b);
        }
        // ensure chunk i's data has landed
        if (ip2 < nch)          asm volatile("cp.async.wait_group 2;" ::: "memory");
        else if (i + 1 < nch)   asm volatile("cp.async.wait_group 1;" ::: "memory");
        else                    asm volatile("cp.async.wait_group 0;" ::: "memory");
        asm volatile("fence.proxy.async.shared::cta;" ::: "memory");
        __syncthreads();
        if (wid == 0 && elect1()) {
            const int bi = i % 3;
            uint64_t da = make_desc(data0 + (uint32_t)bi * 32768u);
            uint64_t db = make_desc(data0 + (uint32_t)bi * 32768u + 16384u);
#pragma unroll
            for (int ks = 0; ks < 4; ks++)
                mma_tf32(tmem, da + ks * 2, db + ks * 2, IDESC_TF32,
                         (i > 0 || ks > 0) ? 1u : 0u);
            if (bi == 0)      TC_COMMIT(MB0);
            else if (bi == 1) TC_COMMIT(MB1);
            else              TC_COMMIT(MB2);
        }
    }
    // drain: exactly one pending commit per buffer (nch >= 4)
    mbar_wait(MB0, ph0);
    mbar_wait(MB1, ph1);
    mbar_wait(MB2, ph2);
    asm volatile("tcgen05.fence::after_thread_sync;" ::: "memory");
#undef ISSUE_CP

    // ---- epilogue: warps 0-3 handle the 128x128 tile ----
    if (wid < 4) {
        float* Crow = C + (long)(m0 + wid * 32 + lane) * N + n0;
        const float* Grow = (mode == 3)
            ? (G + (long)(m0 + wid * 32 + lane) * N + n0) : nullptr;
#pragma unroll
        for (int cb = 0; cb < 128; cb += 32) {
            uint32_t r[32];
            LDTM_X32(r, tmem + cb);
            asm volatile("tcgen05.wait::ld.sync.aligned;" ::: "memory");
            if (mode == 4) {
#pragma unroll
                for (int j = 0; j < 32; j++)
                    atomicAdd(Crow + cb + j, alpha * __uint_as_float(r[j]));
            } else {
#pragma unroll
                for (int j = 0; j < 32; j += 4) {
                    float4 v;
                    v.x = __uint_as_float(r[j + 0]);
                    v.y = __uint_as_float(r[j + 1]);
                    v.z = __uint_as_float(r[j + 2]);
                    v.w = __uint_as_float(r[j + 3]);
                    if (mode == 0) {
                        v.x *= alpha; v.y *= alpha; v.z *= alpha; v.w *= alpha;
                    } else if (mode == 1) {
                        float4 c = *(const float4*)(Crow + cb + j);
                        v.x = fmaf(alpha, v.x, c.x); v.y = fmaf(alpha, v.y, c.y);
                        v.z = fmaf(alpha, v.z, c.z); v.w = fmaf(alpha, v.w, c.w);
                    } else if (mode == 2) {
                        v.x = silu_f(fminf(5.f, fmaxf(-5.f, v.x)));
                        v.y = silu_f(fminf(5.f, fmaxf(-5.f, v.y)));
                        v.z = silu_f(fminf(5.f, fmaxf(-5.f, v.z)));
                        v.w = silu_f(fminf(5.f, fmaxf(-5.f, v.w)));
                    } else {
                        float4 g = *(const float4*)(Grow + cb + j);
                        v.x *= silu_f(g.x); v.y *= silu_f(g.y);
                        v.z *= silu_f(g.z); v.w *= silu_f(g.w);
                    }
                    if (rnd) {
                        v.x = rndf(v.x); v.y = rndf(v.y);
                        v.z = rndf(v.z); v.w = rndf(v.w);
                    }
                    *(float4*)(Crow + cb + j) = v;
                }
            }
        }
    }
    asm volatile("tcgen05.fence::before_thread_sync;" ::: "memory");
    __syncthreads();
    if (wid == 0) {
        asm volatile("tcgen05.dealloc.cta_group::1.sync.aligned.b32 %0, %1;"
                     :: "r"(tmem), "r"(128u));
    }
#else
    // -------------------- mma.sync tf32 fallback (compile-only safety net) --------------------
    uint32_t* As = (uint32_t*)smem;
    uint32_t* Bs = As + 128 * 36;

    const int warpM = wid >> 2, warpN = wid & 3;
    const int g  = lane >> 2;
    const int tk = lane & 3;

    float acc[4][4][4];
#pragma unroll
    for (int mt = 0; mt < 4; mt++)
#pragma unroll
        for (int nt = 0; nt < 4; nt++)
#pragma unroll
            for (int j = 0; j < 4; j++) acc[mt][nt][j] = 0.f;

    for (int i = 0; i < nch; i++) {
        __syncthreads();
        const int k0 = i << 5;
#pragma unroll
        for (int it = 0; it < 8; it++) {
            int idx = it * 256 + tid;
            int r = idx >> 3, q = idx & 7;
            const float* src = (r < 128) ? (Ap + (long)r * K) : (Bp + (long)(r - 128) * K);
            float4 v = *(const float4*)(src + k0 + q * 4);
            uint4 u = make_uint4(f2tf32(v.x), f2tf32(v.y), f2tf32(v.z), f2tf32(v.w));
            *(uint4*)(As + r * 36 + q * 4) = u;
        }
        __syncthreads();
#pragma unroll
        for (int kk = 0; kk < 4; kk++) {
            uint32_t af[4][4];
#pragma unroll
            for (int mt = 0; mt < 4; mt++) {
                int ra = warpM * 64 + mt * 16 + g;
                af[mt][0] = As[ra * 36 + kk * 8 + tk];
                af[mt][1] = As[(ra + 8) * 36 + kk * 8 + tk];
                af[mt][2] = As[ra * 36 + kk * 8 + tk + 4];
                af[mt][3] = As[(ra + 8) * 36 + kk * 8 + tk + 4];
            }
            uint32_t bf[4][2];
#pragma unroll
            for (int nt = 0; nt < 4; nt++) {
                int rb = warpN * 32 + nt * 8 + g;
                bf[nt][0] = Bs[rb * 36 + kk * 8 + tk];
                bf[nt][1] = Bs[rb * 36 + kk * 8 + tk + 4];
            }
#pragma unroll
            for (int mt = 0; mt < 4; mt++)
#pragma unroll
                for (int nt = 0; nt < 4; nt++) {
                    asm volatile(
                        "mma.sync.aligned.m16n8k8.row.col.f32.tf32.tf32.f32 "
                        "{%0,%1,%2,%3}, {%4,%5,%6,%7}, {%8,%9}, {%0,%1,%2,%3};"
                        : "+f"(acc[mt][nt][0]), "+f"(acc[mt][nt][1]),
                          "+f"(acc[mt][nt][2]), "+f"(acc[mt][nt][3])
                        : "r"(af[mt][0]), "r"(af[mt][1]), "r"(af[mt][2]), "r"(af[mt][3]),
                          "r"(bf[nt][0]), "r"(bf[nt][1]));
                }
        }
    }
#pragma unroll
    for (int mt = 0; mt < 4; mt++)
#pragma unroll
        for (int nt = 0; nt < 4; nt++)
#pragma unroll
            for (int j = 0; j < 4; j++) {
                int row = m0 + warpM * 64 + mt * 16 + g + ((j >= 2) ? 8 : 0);
                int col = n0 + warpN * 32 + nt * 8 + tk * 2 + (j & 1);
                long ci = (long)row * N + col;
                float a = acc[mt][nt][j];
                float v;
                if (mode == 4) { atomicAdd(C + ci, alpha * a); continue; }
                else if (mode == 0) v = alpha * a;
                else if (mode == 1) v = fmaf(alpha, a, C[ci]);
                else if (mode == 2) v = silu_f(fminf(5.f, fmaxf(-5.f, a)));
                else                v = silu_f(G[ci]) * a;
                if (rnd) v = rndf(v);
                C[ci] = v;
            }
#endif
}

// ============================================================
// Small helpers
// ============================================================
__global__ void zero_kernel(float* p, long n)
{
    long i = (long)blockIdx.x * blockDim.x + threadIdx.x;
    long stride = (long)gridDim.x * blockDim.x;
    for (; i < n; i += stride) p[i] = 0.f;
}

// out[i] = tf32_rna(in[i]) kept in fp32 container (n % 4 == 0)
__global__ void rnd_kernel(const float* __restrict__ in, float* __restrict__ out, long n)
{
    long i = (long)blockIdx.x * blockDim.x + threadIdx.x;
    long stride = (long)gridDim.x * blockDim.x;
    for (long j = i * 4; j < n; j += stride * 4) {
        float4 v = *(const float4*)(in + j);
        v.x = rndf(v.x); v.y = rndf(v.y); v.z = rndf(v.z); v.w = rndf(v.w);
        *(float4*)(out + j) = v;
    }
}

// out[b][c][r] = rnd(in[b][r][c])
__global__ void transpose_kernel(const float* __restrict__ in, float* __restrict__ out,
                                 int R, int C, long sIn, long sOut)
{
    __shared__ float tile[32][33];
    in  += (long)blockIdx.z * sIn;
    out += (long)blockIdx.z * sOut;
    int r0 = blockIdx.y * 32, c0 = blockIdx.x * 32;
    int tx = threadIdx.x, ty = threadIdx.y;
#pragma unroll
    for (int i = 0; i < 32; i += 8)
        tile[ty + i][tx] = in[(long)(r0 + ty + i) * C + c0 + tx];
    __syncthreads();
#pragma unroll
    for (int i = 0; i < 32; i += 8)
        out[(long)(c0 + ty + i) * R + r0 + tx] = rndf(tile[tx][ty + i]);
}

__device__ __forceinline__ float2 block_mean_var_128(float v)
{
    float s = v, s2 = v * v;
#pragma unroll
    for (int o = 16; o > 0; o >>= 1) {
        s  += __shfl_xor_sync(0xffffffffu, s,  o);
        s2 += __shfl_xor_sync(0xffffffffu, s2, o);
    }
    __shared__ float sh[8];
    int w = threadIdx.x >> 5;
    if ((threadIdx.x & 31) == 0) { sh[w] = s; sh[4 + w] = s2; }
    __syncthreads();
    s  = sh[0] + sh[1] + sh[2] + sh[3];
    s2 = sh[4] + sh[5] + sh[6] + sh[7];
    __syncthreads();
    float m = s * (1.f / 128.f);
    return make_float2(m, s2 * (1.f / 128.f) - m * m);
}

// LN over rows of length 128, tf32-rounded output (feeds GEMMs only)
__global__ void ln_kernel(const float* __restrict__ in, float* __restrict__ out,
                          const float* __restrict__ g, const float* __restrict__ b)
{
    long row = blockIdx.x;
    int  t   = threadIdx.x;
    float v  = in[row * 128 + t];
    float2 mv = block_mean_var_128(v);
    float inv = rsqrtf(mv.y + 1e-5f);
    out[row * 128 + t] = rndf((v - mv.x) * inv * g[t] + b[t]);
}

__global__ void expert_select_kernel(const float* __restrict__ ew,
                                     const float* __restrict__ Eall,
                                     const float* __restrict__ eln_g,
                                     const float* __restrict__ eln_b,
                                     float* __restrict__ Ecomp)
{
    long m = blockIdx.x;
    int  t = threadIdx.x;
    __shared__ int sidx;
    if (t == 0) {
        int idx = -1;
        const float* w = ew + m * EE;
#pragma unroll
        for (int i = 0; i < EE; i++) if (w[i] > 0.f) idx = i;
        sidx = idx;
    }
    __syncthreads();
    int idx = sidx;
    float o = 0.f;
    if (idx >= 0) {
        float v = Eall[m * (EE * AA) + idx * AA + t];
        float2 mv = block_mean_var_128(v);
        float inv = rsqrtf(mv.y + 1e-5f);
        o = rndf((v - mv.x) * inv * eln_g[idx * AA + t] + eln_b[idx * AA + t]);
    }
    Ecomp[m * AA + t] = o;
}

// ============================================================
// Launch
// ============================================================
extern "C" void kernel_launch(void* const* d_in, const int* in_sizes, int n_in,
                              void* d_out, int out_size)
{
    const float* x       = (const float*)d_in[0];
    const float* ew      = (const float*)d_in[1];
    const float* w_up    = (const float*)d_in[2];
    const float* w_gate  = (const float*)d_in[3];
    const float* w_down  = (const float*)d_in[4];
    const float* w_pre   = (const float*)d_in[5];
    const float* w_post  = (const float*)d_in[6];
    const float* an_g    = (const float*)d_in[7];
    const float* an_b    = (const float*)d_in[8];
    const float* w_aproj = (const float*)d_in[9];
    const float* w_exp   = (const float*)d_in[10];
    const float* eln_g   = (const float*)d_in[11];
    const float* eln_b   = (const float*)d_in[12];
    const float* w_eproj = (const float*)d_in[13];
    const float* w_out   = (const float*)d_in[14];
    float* out = (float*)d_out;

    float *Yg, *Hid, *Pre, *PreR, *Ain, *Post, *Aout, *AiT, *AW, *Adapt, *AdaptR,
          *Eall, *Ecomp, *Wcomb, *WcombR, *W2, *W2R, *Tep, *Tap,
          *xR, *WgR, *WuR, *WdR, *WoutR, *WpreR, *WpostR, *WexpR;
    cudaGetSymbolAddress((void**)&Yg,     g_Yg);
    cudaGetSymbolAddress((void**)&Hid,    g_Hid);
    cudaGetSymbolAddress((void**)&Pre,    g_Pre);
    cudaGetSymbolAddress((void**)&PreR,   g_PreR);
    cudaGetSymbolAddress((void**)&Ain,    g_Ain);
    cudaGetSymbolAddress((void**)&Post,   g_Post);
    cudaGetSymbolAddress((void**)&Aout,   g_Aout);
    cudaGetSymbolAddress((void**)&AiT,    g_AiT);
    cudaGetSymbolAddress((void**)&AW,     g_AW);
    cudaGetSymbolAddress((void**)&Adapt,  g_Adapt);
    cudaGetSymbolAddress((void**)&AdaptR, g_AdaptR);
    cudaGetSymbolAddress((void**)&Eall,   g_Eall);
    cudaGetSymbolAddress((void**)&Ecomp,  g_Ecomp);
    cudaGetSymbolAddress((void**)&Wcomb,  g_Wcomb);
    cudaGetSymbolAddress((void**)&WcombR, g_WcombR);
    cudaGetSymbolAddress((void**)&W2,     g_W2);
    cudaGetSymbolAddress((void**)&W2R,    g_W2R);
    cudaGetSymbolAddress((void**)&Tep,    g_Tep);
    cudaGetSymbolAddress((void**)&Tap,    g_Tap);
    cudaGetSymbolAddress((void**)&xR,     g_xR);
    cudaGetSymbolAddress((void**)&WgR,    g_WgR);
    cudaGetSymbolAddress((void**)&WuR,    g_WuR);
    cudaGetSymbolAddress((void**)&WdR,    g_WdR);
    cudaGetSymbolAddress((void**)&WoutR,  g_WoutR);
    cudaGetSymbolAddress((void**)&WpreR,  g_WpreR);
    cudaGetSymbolAddress((void**)&WpostR, g_WpostR);
    cudaGetSymbolAddress((void**)&WexpR,  g_WexpR);

    cudaFuncSetAttribute(tc_gemm, cudaFuncAttributeMaxDynamicSharedMemorySize, TCG_SMEM);

    dim3 tb32(32, 8);

    // ---- round raw inputs to tf32 once ----
    rnd_kernel<<<512, 256>>>(x,      xR,     (long)MM * DD);
    rnd_kernel<<<128, 256>>>(w_gate, WgR,    (long)HH * DD);
    rnd_kernel<<<128, 256>>>(w_up,   WuR,    (long)HH * DD);
    rnd_kernel<<<128, 256>>>(w_down, WdR,    (long)DD * HH);
    rnd_kernel<<<128, 256>>>(w_out,  WoutR,  (long)DD * HH);
    rnd_kernel<<<32,  256>>>(w_pre,  WpreR,  (long)AA * DD);
    rnd_kernel<<<32,  256>>>(w_post, WpostR, (long)AA * HH);
    rnd_kernel<<<32,  256>>>(w_exp,  WexpR,  (long)EE * AA * AA);

    // ---- zero split-K atomic targets ----
    zero_kernel<<<64,  256>>>(Wcomb, (long)DD * AA);
    zero_kernel<<<64,  256>>>(W2,    (long)DD * AA);
    zero_kernel<<<256, 256>>>(Pre,   (long)MM * AA);
    zero_kernel<<<256, 256>>>(Post,  (long)MM * AA);
    zero_kernel<<<256, 256>>>(Adapt, (long)MM * AA);

    // ---- weight-only precomputes (split-K 16, atomic) ----
    transpose_kernel<<<dim3(AA / 32, HH / 32, 1), tb32>>>(w_eproj, Tep, HH, AA, 0, 0);
    transpose_kernel<<<dim3(AA / 32, HH / 32, 1), tb32>>>(w_aproj, Tap, HH, AA, 0, 0);
    tc_gemm<<<dim3(1, DD / 128, 16), 256, TCG_SMEM>>>(WoutR, Tep, Wcomb, nullptr,
                                                      DD, AA, HH, 0, 0, 0, 1.f, 4, 16, 0);
    tc_gemm<<<dim3(1, DD / 128, 16), 256, TCG_SMEM>>>(WdR, Tap, W2, nullptr,
                                                      DD, AA, HH, 0, 0, 0, 1.f, 4, 16, 0);
    rnd_kernel<<<32, 256>>>(Wcomb, WcombR, (long)DD * AA);
    rnd_kernel<<<32, 256>>>(W2,    W2R,    (long)DD * AA);

    // ---- gate, then fused up*silu(gate) -> Hid (rounded) ----
    tc_gemm<<<dim3(HH / 128, MM / 128, 1), 256, TCG_SMEM>>>(xR, WgR, Yg, nullptr,
                                                            MM, HH, DD, 0, 0, 0, 1.f, 0, 1, 0);
    tc_gemm<<<dim3(HH / 128, MM / 128, 1), 256, TCG_SMEM>>>(xR, WuR, Hid, Yg,
                                                            MM, HH, DD, 0, 0, 0, 1.f, 3, 1, 1);

    // ---- pre / adapt_in ----
    tc_gemm<<<dim3(1, MM / 128, 2), 256, TCG_SMEM>>>(xR, WpreR, Pre, nullptr,
                                                     MM, AA, DD, 0, 0, 0, 1.f, 4, 2, 0);
    rnd_kernel<<<256, 256>>>(Pre, PreR, (long)MM * AA);
    ln_kernel<<<MM, 128>>>(Pre, Ain, an_g, an_b);

    // ---- post / adapt_out ----
    tc_gemm<<<dim3(1, MM / 128, 2), 256, TCG_SMEM>>>(Hid, WpostR, Post, nullptr,
                                                     MM, AA, HH, 0, 0, 0, 1.f, 4, 2, 0);
    ln_kernel<<<MM, 128>>>(Post, Aout, an_g, an_b);

    // ---- adapt attention (fused silu-clip epilogue, rounded) ----
    transpose_kernel<<<dim3(AA / 32, SS / 32, BB), tb32>>>(Ain, AiT, SS, AA,
                                                           (long)SS * AA, (long)SS * AA);
    tc_gemm<<<dim3(SS / 128, SS / 128, BB), 256, TCG_SMEM>>>(Ain, Aout, AW, nullptr,
                                                             SS, SS, AA,
                                                             (long)SS * AA, (long)SS * AA,
                                                             (long)SS * SS, 1.f, 2, 1, 1);
    tc_gemm<<<dim3(1, SS / 128, BB * 2), 256, TCG_SMEM>>>(AW, AiT, Adapt, nullptr,
                                                          SS, AA, SS,
                                                          (long)SS * SS, (long)AA * SS,
                                                          (long)SS * AA, 1.f, 4, 2, 0);
    rnd_kernel<<<256, 256>>>(Adapt, AdaptR, (long)MM * AA);

    // ---- out = Hid @ w_down^T (exact stores) ----
    tc_gemm<<<dim3(DD / 128, MM / 128, 1), 256, TCG_SMEM>>>(Hid, WdR, out, nullptr,
                                                            MM, DD, HH, 0, 0, 0, 1.f, 0, 1, 0);
    // out += 0.1 * AdaptR @ W2R^T
    tc_gemm<<<dim3(DD / 128, MM / 128, 1), 256, TCG_SMEM>>>(AdaptR, W2R, out, nullptr,
                                                            MM, DD, AA, 0, 0, 0, 0.1f, 1, 1, 0);

    // ---- experts ----
    tc_gemm<<<dim3(EE * AA / 128, MM / 128, 1), 256, TCG_SMEM>>>(PreR, WexpR, Eall, nullptr,
                                                                 MM, EE * AA, AA,
                                                                 0, 0, 0, 1.f, 0, 1, 0);
    expert_select_kernel<<<MM, 128>>>(ew, Eall, eln_g, eln_b, Ecomp);
    // out += 0.1 * Ecomp @ WcombR^T
    tc_gemm<<<dim3(DD / 128, MM / 128, 1), 256, TCG_SMEM>>>(Ecomp, WcombR, out, nullptr,
                                                            MM, DD, AA, 0, 0, 0, 0.1f, 1, 1, 0);
}